// round 3
// baseline (speedup 1.0000x reference)
#include <cuda_runtime.h>
#include <math.h>

// ---------------------------------------------------------------------------
// Problem constants
// ---------------------------------------------------------------------------
#define BB    4          // batch
#define SEQ   3072       // tokens (48*64)
#define DIMC  768        // model dim
#define NH    3          // heads
#define HDIM  256        // head dim
#define DD    262        // head dim + 6 positional
#define BHN   12         // BB*NH
#define HD3   786        // NH*DD

// ---------------------------------------------------------------------------
// Scratch (device globals: the sanctioned alloc-free scratch mechanism)
// ---------------------------------------------------------------------------
static __device__ float g_qkvP[(size_t)3 * BHN * SEQ * HDIM];   // 113 MB  [s][bh][n][d]
static __device__ float g_attn[(size_t)BHN * SEQ * SEQ];        // 453 MB  [bh][n][m]
static __device__ float g_vcat[(size_t)BHN * SEQ * DD];         // 38.6 MB [bh][n][e]
static __device__ float g_f1  [(size_t)BHN * DD * SEQ];         // 38.6 MB [bh][d][m]
static __device__ float g_fund[(size_t)BHN * DD * DD];          // 3.3 MB  [bh][d][e]
static __device__ float g_fundT[(size_t)BB * DD * HD3];         // 3.3 MB  [b][e][h*DD+d]
static __device__ float g_rmax[BHN * SEQ];
static __device__ float g_rinv[BHN * SEQ];
static __device__ float g_cmax[BHN * SEQ];
static __device__ float g_cinv[BHN * SEQ];

// ---------------------------------------------------------------------------
// Generic 128x128x16 tiled fp32 GEMM, 256 threads, 8x8 register tile.
//   C[i,j] = alpha * sum_k A(i,k) * B(j,k)   (+ epilogue variants)
// AMODE 0: A[i*lda + k]  (k contiguous)     AMODE 1: A[k*lda + i] (i contiguous)
// BMODE 0: B[j*ldb + k]  (k contiguous)     BMODE 1: B[k*ldb + j] (j contiguous)
// EPI 0: plain store; EPI 1: QKV scatter to g_qkvP layout; EPI 2: += bias[j]
// ---------------------------------------------------------------------------
template<int AMODE, int BMODE, int EPI>
__global__ void __launch_bounds__(256, 2) gemm_k(
    const float* __restrict__ A, const float* __restrict__ B,
    float* __restrict__ C, const float* __restrict__ bias,
    int M, int N, int K, int lda, int ldb, int ldc,
    long long sA, long long sB, long long sC, float alpha)
{
    A += (long long)blockIdx.z * sA;
    B += (long long)blockIdx.z * sB;
    C += (long long)blockIdx.z * sC;
    const int i0 = blockIdx.y * 128;
    const int j0 = blockIdx.x * 128;

    __shared__ float As[16][128];
    __shared__ float Bs[16][128];

    float acc[8][8];
#pragma unroll
    for (int r = 0; r < 8; r++)
#pragma unroll
        for (int c = 0; c < 8; c++) acc[r][c] = 0.f;

    const int tid = threadIdx.x;
    const int tx = tid & 15;
    const int ty = tid >> 4;

    for (int k0 = 0; k0 < K; k0 += 16) {
        // ---- A tile -> As[k][i]
        if (AMODE == 0) {
#pragma unroll
            for (int rep = 0; rep < 2; rep++) {
                int t  = tid + rep * 256;
                int i  = t >> 2;
                int kg = (t & 3) * 4;
                int gi = i0 + i;
                const float* ap = A + (long long)gi * lda + k0 + kg;
                bool iok = gi < M;
#pragma unroll
                for (int c = 0; c < 4; c++) {
                    int gk = k0 + kg + c;
                    As[kg + c][i] = (iok && gk < K) ? ap[c] : 0.f;
                }
            }
        } else {
#pragma unroll
            for (int rep = 0; rep < 2; rep++) {
                int t  = tid + rep * 256;
                int k  = t >> 5;
                int ig = (t & 31) * 4;
                int gk = k0 + k;
                const float* ap = A + (long long)gk * lda + i0 + ig;
                bool kok = gk < K;
#pragma unroll
                for (int c = 0; c < 4; c++) {
                    int gi = i0 + ig + c;
                    As[k][ig + c] = (kok && gi < M) ? ap[c] : 0.f;
                }
            }
        }
        // ---- B tile -> Bs[k][j]
        if (BMODE == 0) {
#pragma unroll
            for (int rep = 0; rep < 2; rep++) {
                int t  = tid + rep * 256;
                int j  = t >> 2;
                int kg = (t & 3) * 4;
                int gj = j0 + j;
                const float* bp = B + (long long)gj * ldb + k0 + kg;
                bool jok = gj < N;
#pragma unroll
                for (int c = 0; c < 4; c++) {
                    int gk = k0 + kg + c;
                    Bs[kg + c][j] = (jok && gk < K) ? bp[c] : 0.f;
                }
            }
        } else {
#pragma unroll
            for (int rep = 0; rep < 2; rep++) {
                int t  = tid + rep * 256;
                int k  = t >> 5;
                int jg = (t & 31) * 4;
                int gk = k0 + k;
                const float* bp = B + (long long)gk * ldb + j0 + jg;
                bool kok = gk < K;
#pragma unroll
                for (int c = 0; c < 4; c++) {
                    int gj = j0 + jg + c;
                    Bs[k][jg + c] = (kok && gj < N) ? bp[c] : 0.f;
                }
            }
        }
        __syncthreads();

#pragma unroll
        for (int kk = 0; kk < 16; kk++) {
            float a[8], b[8];
#pragma unroll
            for (int r = 0; r < 8; r++) a[r] = As[kk][ty * 8 + r];
#pragma unroll
            for (int c = 0; c < 8; c++) b[c] = Bs[kk][tx * 8 + c];
#pragma unroll
            for (int r = 0; r < 8; r++)
#pragma unroll
                for (int c = 0; c < 8; c++)
                    acc[r][c] = fmaf(a[r], b[c], acc[r][c]);
        }
        __syncthreads();
    }

    // ---- epilogue
#pragma unroll
    for (int r = 0; r < 8; r++) {
        int gi = i0 + ty * 8 + r;
        if (gi >= M) continue;
#pragma unroll
        for (int c = 0; c < 8; c++) {
            int gj = j0 + tx * 8 + c;
            if (gj >= N) continue;
            float v = acc[r][c] * alpha;
            if (EPI == 2) v += bias[gj];
            if (EPI == 1) {
                // scatter qkv column j=(s,h,d), row i=(b,n) -> g_qkvP[s][b*NH+h][n][d]
                int s  = gj / DIMC;
                int rc = gj - s * DIMC;
                int h  = rc >> 8;
                int d  = rc & 255;
                int b_ = gi / SEQ;
                int n  = gi - b_ * SEQ;
                long long dst = ((((long long)s * BHN) + (b_ * NH + h)) * SEQ + n) * HDIM + d;
                C[dst] = v;
            } else {
                C[(long long)gi * ldc + gj] = v;
            }
        }
    }
}

// ---------------------------------------------------------------------------
// Row softmax stats: per attn row -> max and 1/sum(exp(a-max))
// ---------------------------------------------------------------------------
__global__ void row_stats(const float* __restrict__ attn,
                          float* __restrict__ rmax, float* __restrict__ rinv)
{
    __shared__ float sm[128];
    const long long row = blockIdx.x;
    const float* a = attn + row * SEQ;
    const int t = threadIdx.x;

    float m = -INFINITY;
    for (int i = t; i < SEQ; i += 128) m = fmaxf(m, a[i]);
    sm[t] = m; __syncthreads();
    for (int off = 64; off > 0; off >>= 1) {
        if (t < off) sm[t] = fmaxf(sm[t], sm[t + off]);
        __syncthreads();
    }
    const float M = sm[0]; __syncthreads();

    float s = 0.f;
    for (int i = t; i < SEQ; i += 128) s += __expf(a[i] - M);
    sm[t] = s; __syncthreads();
    for (int off = 64; off > 0; off >>= 1) {
        if (t < off) sm[t] += sm[t + off];
        __syncthreads();
    }
    if (t == 0) { rmax[row] = M; rinv[row] = 1.f / sm[0]; }
}

// ---------------------------------------------------------------------------
// Column softmax stats: online max/sum per column, single pass over attn
// ---------------------------------------------------------------------------
__global__ void col_stats(const float* __restrict__ attn,
                          float* __restrict__ cmax, float* __restrict__ cinv)
{
    const int bh = blockIdx.y;
    const int m  = blockIdx.x * 128 + threadIdx.x;
    const float* a = attn + (long long)bh * SEQ * SEQ + m;

    float mx[4] = {-INFINITY, -INFINITY, -INFINITY, -INFINITY};
    float ss[4] = {0.f, 0.f, 0.f, 0.f};
    for (int n = 0; n < SEQ; n += 4) {
#pragma unroll
        for (int u = 0; u < 4; u++) {
            float v = a[(long long)(n + u) * SEQ];
            if (v <= mx[u]) {
                ss[u] += __expf(v - mx[u]);
            } else {
                ss[u] = ss[u] * __expf(mx[u] - v) + 1.f;
                mx[u] = v;
            }
        }
    }
    float M = fmaxf(fmaxf(mx[0], mx[1]), fmaxf(mx[2], mx[3]));
    float S = 0.f;
#pragma unroll
    for (int u = 0; u < 4; u++) S += ss[u] * __expf(mx[u] - M);
    cmax[bh * SEQ + m] = M;
    cinv[bh * SEQ + m] = 1.f / S;
}

// ---------------------------------------------------------------------------
// attn_f = softmax_row(a) * softmax_col(a) = exp(2a - rmax - cmax)*rinv*cinv
// ---------------------------------------------------------------------------
__global__ void apply_softmax(float4* __restrict__ attn,
                              const float* __restrict__ rmax, const float* __restrict__ rinv,
                              const float* __restrict__ cmax, const float* __restrict__ cinv)
{
    const long long id = (long long)blockIdx.x * blockDim.x + threadIdx.x;  // float4 index
    if (id >= (long long)BHN * SEQ * SEQ / 4) return;
    const long long base = id * 4;
    const int m0 = (int)(base % SEQ);
    const long long rg = base / SEQ;          // global row (bh*SEQ + n)
    const int bh = (int)(rg / SEQ);

    const float rm = rmax[rg];
    const float ri = rinv[rg];
    const float4 cm = *(const float4*)(cmax + (long long)bh * SEQ + m0);
    const float4 ci = *(const float4*)(cinv + (long long)bh * SEQ + m0);

    float4 v = attn[id];
    v.x = __expf(2.f * v.x - rm - cm.x) * ri * ci.x;
    v.y = __expf(2.f * v.y - rm - cm.y) * ri * ci.y;
    v.z = __expf(2.f * v.z - rm - cm.z) * ri * ci.z;
    v.w = __expf(2.f * v.w - rm - cm.w) * ri * ci.w;
    attn[id] = v;
}

// ---------------------------------------------------------------------------
// v_cat[bh][n][0:256] = v ; [256:262] = (y^2, x^2, xy, y, x, 1)
// ---------------------------------------------------------------------------
__global__ void build_vcat(const float* __restrict__ qkvP, float* __restrict__ vcat)
{
    const int rid = blockIdx.x;          // bh*SEQ + n
    const int bh  = rid / SEQ;
    const int n   = rid - bh * SEQ;
    const float* src = qkvP + ((long long)(2 * BHN + bh) * SEQ + n) * HDIM;
    float* dst = vcat + (long long)rid * DD;
    const int t = threadIdx.x;
    dst[t] = src[t];
    if (t < 6) {
        int iy = n % 48;
        int ix = n / 48;
        float y = -1.f + 2.f * (float)iy / 47.f;
        float x = -1.f + 2.f * (float)ix / 63.f;
        float p = (t == 0) ? y * y :
                  (t == 1) ? x * x :
                  (t == 2) ? y * x :
                  (t == 3) ? y :
                  (t == 4) ? x : 1.f;
        dst[HDIM + t] = p;
    }
}

// ---------------------------------------------------------------------------
// fundT[b][e][h*DD+d] = fund[bh][d][e]   (reshape + transpose(0,2,1))
// ---------------------------------------------------------------------------
__global__ void transpose_fund(const float* __restrict__ fund, float* __restrict__ fundT)
{
    const long long idx = (long long)blockIdx.x * blockDim.x + threadIdx.x;
    if (idx >= (long long)BHN * DD * DD) return;
    const int e  = (int)(idx % DD);
    const long long r = idx / DD;
    const int d  = (int)(r % DD);
    const int bh = (int)(r / DD);
    const int b  = bh / NH;
    const int h  = bh - b * NH;
    fundT[((long long)b * DD + e) * HD3 + h * DD + d] = fund[idx];
}

// ---------------------------------------------------------------------------
// Launch
// ---------------------------------------------------------------------------
extern "C" void kernel_launch(void* const* d_in, const int* in_sizes, int n_in,
                              void* d_out, int out_size)
{
    const float* x    = (const float*)d_in[0];  // [4,3072,768]
    const float* Wqkv = (const float*)d_in[1];  // [2304,768]
    const float* Wpf  = (const float*)d_in[2];  // [768,786]
    const float* bpf  = (const float*)d_in[3];  // [768]
    float* out = (float*)d_out;                 // [4,262,768]

    float *qkvP, *attn, *vcat, *f1, *fund, *fundT, *rmax, *rinv, *cmax, *cinv;
    cudaGetSymbolAddress((void**)&qkvP,  g_qkvP);
    cudaGetSymbolAddress((void**)&attn,  g_attn);
    cudaGetSymbolAddress((void**)&vcat,  g_vcat);
    cudaGetSymbolAddress((void**)&f1,    g_f1);
    cudaGetSymbolAddress((void**)&fund,  g_fund);
    cudaGetSymbolAddress((void**)&fundT, g_fundT);
    cudaGetSymbolAddress((void**)&rmax,  g_rmax);
    cudaGetSymbolAddress((void**)&rinv,  g_rinv);
    cudaGetSymbolAddress((void**)&cmax,  g_cmax);
    cudaGetSymbolAddress((void**)&cinv,  g_cinv);

    const long long sQ = (long long)SEQ * HDIM;

    // 1) QKV projection, scattered to [s][bh][n][d]
    gemm_k<0, 0, 1><<<dim3((3 * DIMC) / 128, (BB * SEQ) / 128, 1), 256>>>(
        x, Wqkv, qkvP, nullptr,
        BB * SEQ, 3 * DIMC, DIMC, DIMC, DIMC, 0, 0, 0, 0, 1.f);

    // 2) attn = scale * q @ k^T   (batched over bh)
    gemm_k<0, 0, 0><<<dim3(SEQ / 128, SEQ / 128, BHN), 256>>>(
        qkvP, qkvP + (long long)BHN * sQ, attn, nullptr,
        SEQ, SEQ, HDIM, HDIM, HDIM, SEQ,
        sQ, sQ, (long long)SEQ * SEQ, 0.0625f);

    // 3) softmax stats
    row_stats<<<BHN * SEQ, 128>>>(attn, rmax, rinv);
    col_stats<<<dim3(SEQ / 128, BHN), 128>>>(attn, cmax, cinv);

    // 4) attn_f in place
    apply_softmax<<<(unsigned)(((long long)BHN * SEQ * SEQ / 4 + 255) / 256), 256>>>(
        (float4*)attn, rmax, rinv, cmax, cinv);

    // 5) v_cat = [v, pos]
    build_vcat<<<BHN * SEQ, 256>>>(qkvP, vcat);

    // 6) f1[d,m] = sum_n v_cat[n,d] * attn_f[n,m]
    gemm_k<1, 1, 0><<<dim3(SEQ / 128, (DD + 127) / 128, BHN), 256>>>(
        vcat, attn, f1, nullptr,
        DD, SEQ, SEQ, DD, SEQ, SEQ,
        (long long)SEQ * DD, (long long)SEQ * SEQ, (long long)DD * SEQ, 1.f);

    // 7) fund[d,e] = sum_m f1[d,m] * v_cat[m,e]
    gemm_k<0, 1, 0><<<dim3((DD + 127) / 128, (DD + 127) / 128, BHN), 256>>>(
        f1, vcat, fund, nullptr,
        DD, DD, SEQ, SEQ, DD, DD,
        (long long)DD * SEQ, (long long)SEQ * DD, (long long)DD * DD, 1.f);

    // 8) reshape/transpose
    transpose_fund<<<(int)(((long long)BHN * DD * DD + 255) / 256), 256>>>(fund, fundT);

    // 9) out[b,e,o] = sum_j fundT[b,e,j] * Wpf[o,j] + bpf[o]
    gemm_k<0, 0, 2><<<dim3(DIMC / 128, (DD + 127) / 128, BB), 256>>>(
        fundT, Wpf, out, bpf,
        DD, DIMC, HD3, HD3, HD3, DIMC,
        (long long)DD * HD3, 0, (long long)DD * DIMC, 1.f);
}

// round 4
// speedup vs baseline: 1.0529x; 1.0529x over previous
#include <cuda_runtime.h>
#include <cuda_bf16.h>
#include <math.h>

// ---------------------------------------------------------------------------
// Problem constants
// ---------------------------------------------------------------------------
#define BB    4          // batch
#define SEQ   3072       // tokens (48*64)
#define DIMC  768        // model dim
#define NH    3          // heads
#define HDIM  256        // head dim
#define DD    262        // head dim + 6 positional
#define BHN   12         // BB*NH
#define HD3   786        // NH*DD
#define NSP   8          // column-stats split factor

// ---------------------------------------------------------------------------
// Scratch (device globals: sanctioned alloc-free scratch)
// ---------------------------------------------------------------------------
static __device__ float          g_qkvP[(size_t)3 * BHN * SEQ * HDIM];  // 113 MB [s][bh][n][d]
static __device__ float          g_attn[(size_t)BHN * SEQ * SEQ];       // 453 MB fp32 logits
static __device__ __nv_bfloat16  g_attnb[(size_t)BHN * SEQ * SEQ];      // 227 MB bf16 attn_f
static __device__ float          g_vcat[(size_t)BHN * SEQ * DD];        // 38.6 MB [bh][n][e]
static __device__ float          g_f1T [(size_t)BHN * SEQ * DD];        // 38.6 MB [bh][m][d]
static __device__ float          g_fund[(size_t)BHN * DD * DD];
static __device__ float          g_fundT[(size_t)BB * DD * HD3];
static __device__ float          g_rmax[BHN * SEQ];
static __device__ float          g_rinv[BHN * SEQ];
static __device__ float          g_cmax[BHN * SEQ];
static __device__ float          g_cinv[BHN * SEQ];
static __device__ float          g_pmax[NSP * BHN * SEQ];
static __device__ float          g_psum[NSP * BHN * SEQ];

// ---------------------------------------------------------------------------
// f32x2 packed FMA (Blackwell dual fp32 pipe; only reachable via explicit PTX)
// ---------------------------------------------------------------------------
__device__ __forceinline__ void ffma2(float2& d, const float2& a, const float2& b) {
    asm("fma.rn.f32x2 %0, %1, %2, %0;"
        : "+l"(*reinterpret_cast<unsigned long long*>(&d))
        : "l"(*reinterpret_cast<const unsigned long long*>(&a)),
          "l"(*reinterpret_cast<const unsigned long long*>(&b)));
}

__device__ __forceinline__ float to_f(float x) { return x; }
__device__ __forceinline__ float to_f(__nv_bfloat16 x) { return __bfloat162float(x); }

// 4-element vector load (8-byte alignment guaranteed at call sites)
__device__ __forceinline__ void ld4(const float* p, float v[4]) {
    float2 a = *(const float2*)p; float2 b = *(const float2*)(p + 2);
    v[0] = a.x; v[1] = a.y; v[2] = b.x; v[3] = b.y;
}
__device__ __forceinline__ void ld4(const __nv_bfloat16* p, float v[4]) {
    uint2 r = *(const uint2*)p;
    __nv_bfloat162 h0 = *reinterpret_cast<const __nv_bfloat162*>(&r.x);
    __nv_bfloat162 h1 = *reinterpret_cast<const __nv_bfloat162*>(&r.y);
    float2 f0 = __bfloat1622float2(h0);
    float2 f1 = __bfloat1622float2(h1);
    v[0] = f0.x; v[1] = f0.y; v[2] = f1.x; v[3] = f1.y;
}

// ---------------------------------------------------------------------------
// 128x128x16 tiled GEMM on the packed-f32x2 pipe. 256 threads, 8x8 outputs
// per thread held as 8x4 float2 pairs.
//   C[i,j] = alpha * sum_k A(i,k) * B(j,k)   (+ epilogues)
// AMODE 0: A[i*lda+k]   AMODE 1: A[k*lda+i]   (TA may be bf16)
// BMODE 0: B[j*ldb+k]   BMODE 1: B[k*ldb+j]
// EPI 0: store; EPI 1: QKV scatter; EPI 2: +bias[j]
// A is stored DUPLICATED in smem: Asd[k][2i]=Asd[k][2i+1]=A(i,k), so the
// broadcast operand of each f32x2 FMA is a single LDS.64.
// ---------------------------------------------------------------------------
template<typename TA, int AMODE, int BMODE, int EPI>
__global__ void __launch_bounds__(256, 2) gemm2_k(
    const TA* __restrict__ A, const float* __restrict__ B,
    float* __restrict__ C, const float* __restrict__ bias,
    int M, int N, int K, int lda, int ldb, int ldc,
    long long sA, long long sB, long long sC, float alpha)
{
    A += (long long)blockIdx.z * sA;
    B += (long long)blockIdx.z * sB;
    C += (long long)blockIdx.z * sC;
    const int i0 = blockIdx.y * 128;
    const int j0 = blockIdx.x * 128;

    __shared__ float Asd[16][256];   // duplicated A
    __shared__ float Bs [16][128];

    float2 acc[8][4];
#pragma unroll
    for (int r = 0; r < 8; r++)
#pragma unroll
        for (int c = 0; c < 4; c++) acc[r][c] = make_float2(0.f, 0.f);

    const int tid = threadIdx.x;
    const int tx  = tid & 15;     // column group
    const int ty  = tid >> 4;     // row group

    for (int k0 = 0; k0 < K; k0 += 16) {
        // ---- A tile (duplicated) ----
        if (AMODE == 0) {
#pragma unroll
            for (int rep = 0; rep < 2; rep++) {
                int t2 = tid + rep * 256;
                int i  = t2 >> 2;
                int kg = (t2 & 3) * 4;
                int gi = i0 + i;
                bool iok = gi < M;
                const TA* ap = A + (long long)gi * lda + k0 + kg;
#pragma unroll
                for (int c = 0; c < 4; c++) {
                    float v = (iok && (k0 + kg + c) < K) ? to_f(ap[c]) : 0.f;
                    *(float2*)&Asd[kg + c][2 * i] = make_float2(v, v);
                }
            }
        } else {
#pragma unroll
            for (int rep = 0; rep < 2; rep++) {
                int t2 = tid + rep * 256;
                int k  = t2 >> 5;
                int ig = (t2 & 31) * 4;
                int gk = k0 + k;
                bool kok = gk < K;
                float v[4];
                if (kok && (i0 + ig + 4) <= M) {
                    ld4(A + (long long)gk * lda + i0 + ig, v);
                } else {
#pragma unroll
                    for (int c = 0; c < 4; c++)
                        v[c] = (kok && (i0 + ig + c) < M)
                             ? to_f(A[(long long)gk * lda + i0 + ig + c]) : 0.f;
                }
                *(float4*)&Asd[k][2 * ig]     = make_float4(v[0], v[0], v[1], v[1]);
                *(float4*)&Asd[k][2 * ig + 4] = make_float4(v[2], v[2], v[3], v[3]);
            }
        }
        // ---- B tile ----
        if (BMODE == 0) {
#pragma unroll
            for (int rep = 0; rep < 2; rep++) {
                int t2 = tid + rep * 256;
                int j  = t2 >> 2;
                int kg = (t2 & 3) * 4;
                int gj = j0 + j;
                bool jok = gj < N;
                const float* bp = B + (long long)gj * ldb + k0 + kg;
#pragma unroll
                for (int c = 0; c < 4; c++)
                    Bs[kg + c][j] = (jok && (k0 + kg + c) < K) ? bp[c] : 0.f;
            }
        } else {
#pragma unroll
            for (int rep = 0; rep < 2; rep++) {
                int t2 = tid + rep * 256;
                int k  = t2 >> 5;
                int jg = (t2 & 31) * 4;
                int gk = k0 + k;
                bool kok = gk < K;
                float v[4];
                if (kok && (j0 + jg + 4) <= N) {
                    ld4(B + (long long)gk * ldb + j0 + jg, v);
                } else {
#pragma unroll
                    for (int c = 0; c < 4; c++)
                        v[c] = (kok && (j0 + jg + c) < N)
                             ? B[(long long)gk * ldb + j0 + jg + c] : 0.f;
                }
                *(float4*)&Bs[k][jg] = make_float4(v[0], v[1], v[2], v[3]);
            }
        }
        __syncthreads();

#pragma unroll
        for (int kk = 0; kk < 16; kk++) {
            float2 a2[8], b2[4];
#pragma unroll
            for (int c = 0; c < 4; c++)
                b2[c] = *(const float2*)&Bs[kk][2 * tx + 32 * c];
#pragma unroll
            for (int r = 0; r < 8; r++)
                a2[r] = *(const float2*)&Asd[kk][2 * (ty + 16 * r)];
#pragma unroll
            for (int r = 0; r < 8; r++)
#pragma unroll
                for (int c = 0; c < 4; c++)
                    ffma2(acc[r][c], a2[r], b2[c]);
        }
        __syncthreads();
    }

    // ---- epilogue: rows gi = i0 + ty + 16r, col pairs gj = j0 + 2tx + 32c ----
#pragma unroll
    for (int r = 0; r < 8; r++) {
        int gi = i0 + ty + 16 * r;
        if (gi >= M) continue;
#pragma unroll
        for (int c = 0; c < 4; c++) {
            int gj = j0 + 2 * tx + 32 * c;
            float2 v = acc[r][c];
            v.x *= alpha; v.y *= alpha;
            if (EPI == 2) {
                if (gj     < N) v.x += bias[gj];
                if (gj + 1 < N) v.y += bias[gj + 1];
            }
            if (EPI == 1) {
#pragma unroll
                for (int e = 0; e < 2; e++) {
                    int gje = gj + e;
                    if (gje >= N) continue;
                    float val = e ? v.y : v.x;
                    int s  = gje / DIMC;
                    int rc = gje - s * DIMC;
                    int h  = rc >> 8;
                    int d  = rc & 255;
                    int b_ = gi / SEQ;
                    int n  = gi - b_ * SEQ;
                    long long dst = ((((long long)s * BHN) + (b_ * NH + h)) * SEQ + n) * HDIM + d;
                    C[dst] = val;
                }
            } else {
                if (gj + 1 < N)      *(float2*)&C[(long long)gi * ldc + gj] = v;
                else if (gj < N)     C[(long long)gi * ldc + gj] = v.x;
            }
        }
    }
}

// ---------------------------------------------------------------------------
// Row softmax stats: 256 threads, row held in registers (3 float4/thread)
// ---------------------------------------------------------------------------
__global__ void row_stats(const float* __restrict__ attn,
                          float* __restrict__ rmax, float* __restrict__ rinv)
{
    __shared__ float sm[256];
    const long long row = blockIdx.x;
    const float4* a = (const float4*)(attn + row * SEQ);
    const int t = threadIdx.x;

    float4 v[3];
#pragma unroll
    for (int u = 0; u < 3; u++) v[u] = a[t + 256 * u];

    float m = -INFINITY;
#pragma unroll
    for (int u = 0; u < 3; u++)
        m = fmaxf(m, fmaxf(fmaxf(v[u].x, v[u].y), fmaxf(v[u].z, v[u].w)));
    sm[t] = m; __syncthreads();
    for (int off = 128; off > 0; off >>= 1) {
        if (t < off) sm[t] = fmaxf(sm[t], sm[t + off]);
        __syncthreads();
    }
    const float M = sm[0]; __syncthreads();

    float s = 0.f;
#pragma unroll
    for (int u = 0; u < 3; u++)
        s += __expf(v[u].x - M) + __expf(v[u].y - M) + __expf(v[u].z - M) + __expf(v[u].w - M);
    sm[t] = s; __syncthreads();
    for (int off = 128; off > 0; off >>= 1) {
        if (t < off) sm[t] += sm[t + off];
        __syncthreads();
    }
    if (t == 0) { rmax[row] = M; rinv[row] = 1.f / sm[0]; }
}

// ---------------------------------------------------------------------------
// Column softmax stats, split over n into NSP chunks (8x the parallelism)
// ---------------------------------------------------------------------------
__global__ void col_stats_part(const float* __restrict__ attn,
                               float* __restrict__ pmax, float* __restrict__ psum)
{
    const int bh = blockIdx.y;
    const int sp = blockIdx.z;
    const int m  = blockIdx.x * 128 + threadIdx.x;
    const float* a = attn + (long long)bh * SEQ * SEQ
                          + (long long)(sp * (SEQ / NSP)) * SEQ + m;

    float mx[4] = {-INFINITY, -INFINITY, -INFINITY, -INFINITY};
    float ss[4] = {0.f, 0.f, 0.f, 0.f};
    for (int n = 0; n < SEQ / NSP; n += 4) {
#pragma unroll
        for (int u = 0; u < 4; u++) {
            float v = a[(long long)(n + u) * SEQ];
            if (v <= mx[u]) {
                ss[u] += __expf(v - mx[u]);
            } else {
                ss[u] = ss[u] * __expf(mx[u] - v) + 1.f;
                mx[u] = v;
            }
        }
    }
    float M = fmaxf(fmaxf(mx[0], mx[1]), fmaxf(mx[2], mx[3]));
    float S = 0.f;
#pragma unroll
    for (int u = 0; u < 4; u++) S += ss[u] * __expf(mx[u] - M);
    pmax[(long long)sp * (BHN * SEQ) + bh * SEQ + m] = M;
    psum[(long long)sp * (BHN * SEQ) + bh * SEQ + m] = S;
}

__global__ void col_stats_comb(const float* __restrict__ pmax, const float* __restrict__ psum,
                               float* __restrict__ cmax, float* __restrict__ cinv)
{
    const int idx = blockIdx.x * 256 + threadIdx.x;
    if (idx >= BHN * SEQ) return;
    float M = -INFINITY;
#pragma unroll
    for (int sp = 0; sp < NSP; sp++) M = fmaxf(M, pmax[sp * (BHN * SEQ) + idx]);
    float S = 0.f;
#pragma unroll
    for (int sp = 0; sp < NSP; sp++)
        S += psum[sp * (BHN * SEQ) + idx] * __expf(pmax[sp * (BHN * SEQ) + idx] - M);
    cmax[idx] = M;
    cinv[idx] = 1.f / S;
}

// ---------------------------------------------------------------------------
// attn_f = exp(2a - rmax - cmax) * rinv * cinv, written as bf16
// ---------------------------------------------------------------------------
__global__ void apply_softmax(const float4* __restrict__ attn,
                              __nv_bfloat16* __restrict__ attnb,
                              const float* __restrict__ rmax, const float* __restrict__ rinv,
                              const float* __restrict__ cmax, const float* __restrict__ cinv)
{
    const long long id = (long long)blockIdx.x * blockDim.x + threadIdx.x;  // float4 index
    if (id >= (long long)BHN * SEQ * SEQ / 4) return;
    const long long base = id * 4;
    const int m0 = (int)(base % SEQ);
    const long long rg = base / SEQ;
    const int bh = (int)(rg / SEQ);

    const float rm = rmax[rg];
    const float ri = rinv[rg];
    const float4 cm = *(const float4*)(cmax + (long long)bh * SEQ + m0);
    const float4 ci = *(const float4*)(cinv + (long long)bh * SEQ + m0);

    float4 v = attn[id];
    float w0 = __expf(2.f * v.x - rm - cm.x) * ri * ci.x;
    float w1 = __expf(2.f * v.y - rm - cm.y) * ri * ci.y;
    float w2 = __expf(2.f * v.z - rm - cm.z) * ri * ci.z;
    float w3 = __expf(2.f * v.w - rm - cm.w) * ri * ci.w;

    __nv_bfloat162 lo = __floats2bfloat162_rn(w0, w1);
    __nv_bfloat162 hi = __floats2bfloat162_rn(w2, w3);
    uint2 packed;
    packed.x = *reinterpret_cast<unsigned int*>(&lo);
    packed.y = *reinterpret_cast<unsigned int*>(&hi);
    *(uint2*)(attnb + base) = packed;
}

// ---------------------------------------------------------------------------
// v_cat[bh][n][0:256] = v ; [256:262] = (y^2, x^2, xy, y, x, 1)
// ---------------------------------------------------------------------------
__global__ void build_vcat(const float* __restrict__ qkvP, float* __restrict__ vcat)
{
    const int rid = blockIdx.x;          // bh*SEQ + n
    const int bh  = rid / SEQ;
    const int n   = rid - bh * SEQ;
    const float* src = qkvP + ((long long)(2 * BHN + bh) * SEQ + n) * HDIM;
    float* dst = vcat + (long long)rid * DD;
    const int t = threadIdx.x;
    dst[t] = src[t];
    if (t < 6) {
        int iy = n % 48;
        int ix = n / 48;
        float y = -1.f + 2.f * (float)iy / 47.f;
        float x = -1.f + 2.f * (float)ix / 63.f;
        float p = (t == 0) ? y * y :
                  (t == 1) ? x * x :
                  (t == 2) ? y * x :
                  (t == 3) ? y :
                  (t == 4) ? x : 1.f;
        dst[HDIM + t] = p;
    }
}

// ---------------------------------------------------------------------------
// fundT[b][e][h*DD+d] = fund[bh][d][e]
// ---------------------------------------------------------------------------
__global__ void transpose_fund(const float* __restrict__ fund, float* __restrict__ fundT)
{
    const long long idx = (long long)blockIdx.x * blockDim.x + threadIdx.x;
    if (idx >= (long long)BHN * DD * DD) return;
    const int e  = (int)(idx % DD);
    const long long r = idx / DD;
    const int d  = (int)(r % DD);
    const int bh = (int)(r / DD);
    const int b  = bh / NH;
    const int h  = bh - b * NH;
    fundT[((long long)b * DD + e) * HD3 + h * DD + d] = fund[idx];
}

// ---------------------------------------------------------------------------
// Launch
// ---------------------------------------------------------------------------
extern "C" void kernel_launch(void* const* d_in, const int* in_sizes, int n_in,
                              void* d_out, int out_size)
{
    const float* x    = (const float*)d_in[0];  // [4,3072,768]
    const float* Wqkv = (const float*)d_in[1];  // [2304,768]
    const float* Wpf  = (const float*)d_in[2];  // [768,786]
    const float* bpf  = (const float*)d_in[3];  // [768]
    float* out = (float*)d_out;                 // [4,262,768]

    float *qkvP, *attn, *vcat, *f1T, *fund, *fundT, *rmax, *rinv, *cmax, *cinv, *pmax, *psum;
    __nv_bfloat16* attnb;
    cudaGetSymbolAddress((void**)&qkvP,  g_qkvP);
    cudaGetSymbolAddress((void**)&attn,  g_attn);
    cudaGetSymbolAddress((void**)&attnb, g_attnb);
    cudaGetSymbolAddress((void**)&vcat,  g_vcat);
    cudaGetSymbolAddress((void**)&f1T,   g_f1T);
    cudaGetSymbolAddress((void**)&fund,  g_fund);
    cudaGetSymbolAddress((void**)&fundT, g_fundT);
    cudaGetSymbolAddress((void**)&rmax,  g_rmax);
    cudaGetSymbolAddress((void**)&rinv,  g_rinv);
    cudaGetSymbolAddress((void**)&cmax,  g_cmax);
    cudaGetSymbolAddress((void**)&cinv,  g_cinv);
    cudaGetSymbolAddress((void**)&pmax,  g_pmax);
    cudaGetSymbolAddress((void**)&psum,  g_psum);

    const long long sQ = (long long)SEQ * HDIM;

    // 1) QKV projection, scattered to [s][bh][n][d]
    gemm2_k<float, 0, 0, 1><<<dim3((3 * DIMC) / 128, (BB * SEQ) / 128, 1), 256>>>(
        x, Wqkv, qkvP, nullptr,
        BB * SEQ, 3 * DIMC, DIMC, DIMC, DIMC, 0, 0, 0, 0, 1.f);

    // 2) attn = scale * q @ k^T   (batched over bh)
    gemm2_k<float, 0, 0, 0><<<dim3(SEQ / 128, SEQ / 128, BHN), 256>>>(
        qkvP, qkvP + (long long)BHN * sQ, attn, nullptr,
        SEQ, SEQ, HDIM, HDIM, HDIM, SEQ,
        sQ, sQ, (long long)SEQ * SEQ, 0.0625f);

    // 3) softmax stats
    row_stats<<<BHN * SEQ, 256>>>(attn, rmax, rinv);
    col_stats_part<<<dim3(SEQ / 128, BHN, NSP), 128>>>(attn, pmax, psum);
    col_stats_comb<<<(BHN * SEQ + 255) / 256, 256>>>(pmax, psum, cmax, cinv);

    // 4) attn_f -> bf16
    apply_softmax<<<(unsigned)(((long long)BHN * SEQ * SEQ / 4 + 255) / 256), 256>>>(
        (const float4*)attn, attnb, rmax, rinv, cmax, cinv);

    // 5) v_cat = [v, pos]
    build_vcat<<<BHN * SEQ, 256>>>(qkvP, vcat);

    // 6) f1T[m,d] = sum_n attn_f[n,m] * v_cat[n,d]   (A = attnb bf16, AMODE1)
    gemm2_k<__nv_bfloat16, 1, 1, 0><<<dim3((DD + 127) / 128, SEQ / 128, BHN), 256>>>(
        attnb, vcat, f1T, nullptr,
        SEQ, DD, SEQ, SEQ, DD, DD,
        (long long)SEQ * SEQ, (long long)SEQ * DD, (long long)SEQ * DD, 1.f);

    // 7) fund[d,e] = sum_m f1T[m,d] * v_cat[m,e]
    gemm2_k<float, 1, 1, 0><<<dim3((DD + 127) / 128, (DD + 127) / 128, BHN), 256>>>(
        f1T, vcat, fund, nullptr,
        DD, DD, SEQ, DD, DD, DD,
        (long long)SEQ * DD, (long long)SEQ * DD, (long long)DD * DD, 1.f);

    // 8) reshape/transpose
    transpose_fund<<<(int)(((long long)BHN * DD * DD + 255) / 256), 256>>>(fund, fundT);

    // 9) out[b,e,o] = sum_j fundT[b,e,j] * Wpf[o,j] + bpf[o]
    gemm2_k<float, 0, 0, 2><<<dim3(DIMC / 128, (DD + 127) / 128, BB), 256>>>(
        fundT, Wpf, out, bpf,
        DD, DIMC, HD3, HD3, HD3, DIMC,
        (long long)DD * HD3, 0, (long long)DD * DIMC, 1.f);
}

// round 8
// speedup vs baseline: 3.6926x; 3.5071x over previous
#include <cuda_runtime.h>
#include <math.h>
#include <cstdint>

// ---------------------------------------------------------------------------
// Problem constants
// ---------------------------------------------------------------------------
#define BB    4
#define SEQ   3072
#define DIMC  768
#define NH    3
#define HDIM  256
#define DD    262
#define BHN   12
#define HD3   786
#define NSP   8

// ---------------------------------------------------------------------------
// Scratch (device globals: sanctioned alloc-free scratch)
// ---------------------------------------------------------------------------
static __device__ float g_qkvP[(size_t)3 * BHN * SEQ * HDIM];  // [s][bh][n][d]
static __device__ float g_attn[(size_t)BHN * SEQ * SEQ];       // attnT: [bh][m][n]
static __device__ float g_vcatT[(size_t)BHN * DD * SEQ];       // [bh][e][n]
static __device__ float g_f1  [(size_t)BHN * DD * SEQ];        // [bh][d][m]
static __device__ float g_fund[(size_t)BHN * DD * DD];
static __device__ float g_fundT[(size_t)BB * DD * HD3];
static __device__ float g_rmax[BHN * SEQ], g_rinv[BHN * SEQ];
static __device__ float g_cmax[BHN * SEQ], g_cinv[BHN * SEQ];
static __device__ float g_pmax[NSP * BHN * SEQ], g_psum[NSP * BHN * SEQ];

// ---------------------------------------------------------------------------
// Helpers (all plain sm_80-era PTX: no "a"-gated instructions)
// ---------------------------------------------------------------------------
__device__ __forceinline__ uint32_t smem_u32(const void* p) {
    uint32_t a;
    asm("{ .reg .u64 t; cvta.to.shared.u64 t, %1; cvt.u32.u64 %0, t; }" : "=r"(a) : "l"(p));
    return a;
}
__device__ __forceinline__ float cvt_tf32(float x) {
    float y; asm("cvt.rna.tf32.f32 %0, %1;" : "=f"(y) : "f"(x)); return y;
}

#define LDSM_X4(r, addr) \
    asm volatile("ldmatrix.sync.aligned.m8n8.x4.shared.b16 {%0,%1,%2,%3}, [%4];" \
        : "=r"((r)[0]), "=r"((r)[1]), "=r"((r)[2]), "=r"((r)[3]) : "r"(addr))

#define MMA_TF32(c, a, b0v, b1v) \
    asm volatile("mma.sync.aligned.m16n8k8.row.col.f32.tf32.tf32.f32 " \
        "{%0,%1,%2,%3}, {%4,%5,%6,%7}, {%8,%9}, {%0,%1,%2,%3};" \
        : "+f"((c)[0]), "+f"((c)[1]), "+f"((c)[2]), "+f"((c)[3]) \
        : "r"((a)[0]), "r"((a)[1]), "r"((a)[2]), "r"((a)[3]), "r"(b0v), "r"(b1v))

// boundary-safe 4-float row load (zero fill)
__device__ __forceinline__ float4 ldg_row(const float* __restrict__ S, int gi, int RM,
                                          int ld, int kk, int K, bool fast)
{
    float4 v = make_float4(0.f, 0.f, 0.f, 0.f);
    if (gi < RM) {
        const float* p = S + (long long)gi * ld + kk;
        if (fast && kk + 4 <= K) {
            v = *(const float4*)p;
        } else {
            if (kk     < K) v.x = p[0];
            if (kk + 1 < K) v.y = p[1];
            if (kk + 2 < K) v.z = p[2];
            if (kk + 3 < K) v.w = p[3];
        }
    }
    return v;
}

// ---------------------------------------------------------------------------
// tf32 tensor-core GEMM via mma.sync (m16n8k8), C[i,j]=alpha*sum_k A(i,k)B(j,k)
// CTA tile 128x128, K-tile 32, 256 threads (8 warps, each 64Mx32N).
// Double-buffered smem (XOR-swizzled for conflict-free ldmatrix).
// EPI 0: plain store; EPI 1: QKV scatter; EPI 2: +bias[j]
// ---------------------------------------------------------------------------
#define STG_A0 0u
#define STG_B0 16384u
#define STG_A1 32768u
#define STG_B1 49152u
static constexpr unsigned SMEM_TOTAL = 65536;

template<int EPI>
__global__ void __launch_bounds__(256) mma_gemm(
    const float* __restrict__ A, const float* __restrict__ B,
    float* __restrict__ C, const float* __restrict__ bias,
    int M, int N, int K, int lda, int ldb, int ldc,
    long long sA, long long sB, long long sC, float alpha)
{
    extern __shared__ char smem[];
    const uint32_t sb = smem_u32(smem);

    A += (long long)blockIdx.z * sA;
    B += (long long)blockIdx.z * sB;
    if (EPI != 1) C += (long long)blockIdx.z * sC;
    const int i0 = blockIdx.y * 128;
    const int j0 = blockIdx.x * 128;

    const int tid  = threadIdx.x;
    const int wid  = tid >> 5, lane = tid & 31;
    const int wm   = wid >> 2, wn = wid & 3;      // warp tile origin (wm*64, wn*32)
    const int g    = lane >> 2, tg = lane & 3;
    const int sub  = lane >> 3, l  = lane & 7;

    // staging assignment: thread -> chunk u (16B), row rs (+32*it)
    const int u  = tid & 7;
    const int rs = tid >> 3;

    // per-lane ldmatrix row bases
    const int halfA = sub >> 1;          // A: k-half from sub>>1, m-half from sub&1
    const int halfB = sub & 1;           // B: k-half from sub&1,  n-half from sub>>1
    uint32_t laOff[4], la7[4], lbOff[2], lb7[2];
#pragma unroll
    for (int m = 0; m < 4; m++) {
        int r = wm * 64 + m * 16 + (sub & 1) * 8 + l;
        laOff[m] = (uint32_t)(r * 128); la7[m] = (uint32_t)(r & 7);
    }
#pragma unroll
    for (int p = 0; p < 2; p++) {
        int r = wn * 32 + p * 16 + (sub >> 1) * 8 + l;
        lbOff[p] = (uint32_t)(r * 128); lb7[p] = (uint32_t)(r & 7);
    }

    float acc[4][4][4];
#pragma unroll
    for (int m = 0; m < 4; m++)
#pragma unroll
        for (int n = 0; n < 4; n++)
#pragma unroll
            for (int e = 0; e < 4; e++) acc[m][n][e] = 0.f;

    const bool fastA = ((lda & 3) == 0);
    const bool fastB = ((ldb & 3) == 0);
    const int  nk    = (K + 31) / 32;

    float4 va[4], vb[4];
    {
        int kk = u * 4;
#pragma unroll
        for (int it = 0; it < 4; it++) {
            va[it] = ldg_row(A, i0 + rs + it * 32, M, lda, kk, K, fastA);
            vb[it] = ldg_row(B, j0 + rs + it * 32, N, ldb, kk, K, fastB);
        }
    }

    for (int kt = 0; kt < nk; kt++) {
        const int s = kt & 1;
        const uint32_t aB = sb + (s ? STG_A1 : STG_A0);
        const uint32_t bB = sb + (s ? STG_B1 : STG_B0);

        // store staged regs -> swizzled smem (tf32-rounded)
        {
            const uint32_t csw = (uint32_t)(u * 16);
#pragma unroll
            for (int it = 0; it < 4; it++) {
                int r = rs + it * 32;
                uint32_t off = (uint32_t)(r * 128) + (csw ^ (uint32_t)((r & 7) << 4));
                uint32_t x0 = __float_as_uint(cvt_tf32(va[it].x));
                uint32_t x1 = __float_as_uint(cvt_tf32(va[it].y));
                uint32_t x2 = __float_as_uint(cvt_tf32(va[it].z));
                uint32_t x3 = __float_as_uint(cvt_tf32(va[it].w));
                asm volatile("st.shared.v4.b32 [%0], {%1,%2,%3,%4};"
                             :: "r"(aB + off), "r"(x0), "r"(x1), "r"(x2), "r"(x3));
                x0 = __float_as_uint(cvt_tf32(vb[it].x));
                x1 = __float_as_uint(cvt_tf32(vb[it].y));
                x2 = __float_as_uint(cvt_tf32(vb[it].z));
                x3 = __float_as_uint(cvt_tf32(vb[it].w));
                asm volatile("st.shared.v4.b32 [%0], {%1,%2,%3,%4};"
                             :: "r"(bB + off), "r"(x0), "r"(x1), "r"(x2), "r"(x3));
            }
        }
        __syncthreads();

        // prefetch next K-tile into regs (overlaps with MMA below)
        if (kt + 1 < nk) {
            int kk = (kt + 1) * 32 + u * 4;
#pragma unroll
            for (int it = 0; it < 4; it++) {
                va[it] = ldg_row(A, i0 + rs + it * 32, M, lda, kk, K, fastA);
                vb[it] = ldg_row(B, j0 + rs + it * 32, N, ldb, kk, K, fastB);
            }
        }

        // MMA over current stage: 4 k-steps of 8
#pragma unroll
        for (int ks = 0; ks < 4; ks++) {
            uint32_t af[4][4], bf[2][4];
#pragma unroll
            for (int m = 0; m < 4; m++) {
                uint32_t ch = (uint32_t)(ks * 2 + halfA) ^ la7[m];
                LDSM_X4(af[m], aB + laOff[m] + (ch << 4));
            }
#pragma unroll
            for (int p = 0; p < 2; p++) {
                uint32_t ch = (uint32_t)(ks * 2 + halfB) ^ lb7[p];
                LDSM_X4(bf[p], bB + lbOff[p] + (ch << 4));
            }
#pragma unroll
            for (int m = 0; m < 4; m++) {
#pragma unroll
                for (int n = 0; n < 4; n++)
                    MMA_TF32(acc[m][n], af[m], bf[n >> 1][(n & 1) * 2], bf[n >> 1][(n & 1) * 2 + 1]);
            }
        }
        // next iteration's __syncthreads (after its STS to the other buffer)
        // orders re-use of this buffer safely.
    }

    // ---- epilogue: direct reg -> gmem (v2 stores; all N are even) ----
#pragma unroll
    for (int m = 0; m < 4; m++) {
        int r0 = i0 + wm * 64 + m * 16 + g;
#pragma unroll
        for (int n = 0; n < 4; n++) {
            int gj = j0 + wn * 32 + n * 8 + 2 * tg;
            if (gj >= N) continue;
            float2 v0 = make_float2(acc[m][n][0] * alpha, acc[m][n][1] * alpha);
            float2 v1 = make_float2(acc[m][n][2] * alpha, acc[m][n][3] * alpha);
            if (EPI == 2) {
                float2 bv = *(const float2*)(bias + gj);
                v0.x += bv.x; v0.y += bv.y; v1.x += bv.x; v1.y += bv.y;
            }
            if (EPI == 1) {
                int s_  = gj / DIMC;
                int rc  = gj - s_ * DIMC;
                int h   = rc >> 8;
                int d   = rc & 255;
#pragma unroll
                for (int hh = 0; hh < 2; hh++) {
                    int gi = r0 + hh * 8;
                    if (gi >= M) continue;
                    int b_ = gi / SEQ, nn = gi - b_ * SEQ;
                    long long dst = ((((long long)s_ * BHN) + (b_ * NH + h)) * SEQ + nn) * HDIM + d;
                    *(float2*)&C[dst] = hh ? v1 : v0;
                }
            } else {
                if (r0 < M)     *(float2*)&C[(long long)r0 * ldc + gj] = v0;
                if (r0 + 8 < M) *(float2*)&C[(long long)(r0 + 8) * ldc + gj] = v1;
            }
        }
    }
}

// ---------------------------------------------------------------------------
// Softmax stats on attnT[m][n].
// Contiguous rows (per m) -> cmax/cinv. Strided cols (per n) -> rmax/rinv.
// ---------------------------------------------------------------------------
__global__ void row_stats(const float* __restrict__ attn,
                          float* __restrict__ omax, float* __restrict__ oinv)
{
    __shared__ float sm[256];
    const long long row = blockIdx.x;
    const float4* a = (const float4*)(attn + row * SEQ);
    const int t = threadIdx.x;

    float4 v[3];
#pragma unroll
    for (int u = 0; u < 3; u++) v[u] = a[t + 256 * u];

    float m = -INFINITY;
#pragma unroll
    for (int u = 0; u < 3; u++)
        m = fmaxf(m, fmaxf(fmaxf(v[u].x, v[u].y), fmaxf(v[u].z, v[u].w)));
    sm[t] = m; __syncthreads();
    for (int off = 128; off > 0; off >>= 1) {
        if (t < off) sm[t] = fmaxf(sm[t], sm[t + off]);
        __syncthreads();
    }
    const float M = sm[0]; __syncthreads();

    float s = 0.f;
#pragma unroll
    for (int u = 0; u < 3; u++)
        s += __expf(v[u].x - M) + __expf(v[u].y - M) + __expf(v[u].z - M) + __expf(v[u].w - M);
    sm[t] = s; __syncthreads();
    for (int off = 128; off > 0; off >>= 1) {
        if (t < off) sm[t] += sm[t + off];
        __syncthreads();
    }
    if (t == 0) { omax[row] = M; oinv[row] = 1.f / sm[0]; }
}

__global__ void col_stats_part(const float* __restrict__ attn,
                               float* __restrict__ pmax, float* __restrict__ psum)
{
    const int bh = blockIdx.y;
    const int sp = blockIdx.z;
    const int n  = blockIdx.x * 128 + threadIdx.x;
    const float* a = attn + (long long)bh * SEQ * SEQ
                          + (long long)(sp * (SEQ / NSP)) * SEQ + n;

    float mx[4] = {-INFINITY, -INFINITY, -INFINITY, -INFINITY};
    float ss[4] = {0.f, 0.f, 0.f, 0.f};
    for (int m = 0; m < SEQ / NSP; m += 4) {
#pragma unroll
        for (int u = 0; u < 4; u++) {
            float v = a[(long long)(m + u) * SEQ];
            if (v <= mx[u]) {
                ss[u] += __expf(v - mx[u]);
            } else {
                ss[u] = ss[u] * __expf(mx[u] - v) + 1.f;
                mx[u] = v;
            }
        }
    }
    float M = fmaxf(fmaxf(mx[0], mx[1]), fmaxf(mx[2], mx[3]));
    float S = 0.f;
#pragma unroll
    for (int u = 0; u < 4; u++) S += ss[u] * __expf(mx[u] - M);
    pmax[(long long)sp * (BHN * SEQ) + bh * SEQ + n] = M;
    psum[(long long)sp * (BHN * SEQ) + bh * SEQ + n] = S;
}

__global__ void col_stats_comb(const float* __restrict__ pmax, const float* __restrict__ psum,
                               float* __restrict__ omax, float* __restrict__ oinv)
{
    const int idx = blockIdx.x * 256 + threadIdx.x;
    if (idx >= BHN * SEQ) return;
    float M = -INFINITY;
#pragma unroll
    for (int sp = 0; sp < NSP; sp++) M = fmaxf(M, pmax[sp * (BHN * SEQ) + idx]);
    float S = 0.f;
#pragma unroll
    for (int sp = 0; sp < NSP; sp++)
        S += psum[sp * (BHN * SEQ) + idx] * __expf(pmax[sp * (BHN * SEQ) + idx] - M);
    omax[idx] = M;
    oinv[idx] = 1.f / S;
}

// ---------------------------------------------------------------------------
// attn_f^T[m][n] = exp(2a - rmax[n] - cmax[m]) * rinv[n] * cinv[m], in place
// ---------------------------------------------------------------------------
__global__ void apply_softmax(float4* __restrict__ attn,
                              const float* __restrict__ rmax, const float* __restrict__ rinv,
                              const float* __restrict__ cmax, const float* __restrict__ cinv)
{
    const long long id = (long long)blockIdx.x * blockDim.x + threadIdx.x;
    if (id >= (long long)BHN * SEQ * SEQ / 4) return;
    const long long base = id * 4;
    const int n0 = (int)(base % SEQ);
    const long long rg = base / SEQ;        // bh*SEQ + m
    const int bh = (int)(rg / SEQ);

    const float cm = cmax[rg];
    const float ci = cinv[rg];
    const float4 rm = *(const float4*)(rmax + (long long)bh * SEQ + n0);
    const float4 ri = *(const float4*)(rinv + (long long)bh * SEQ + n0);

    float4 v = attn[id];
    v.x = __expf(2.f * v.x - rm.x - cm) * ri.x * ci;
    v.y = __expf(2.f * v.y - rm.y - cm) * ri.y * ci;
    v.z = __expf(2.f * v.z - rm.z - cm) * ri.z * ci;
    v.w = __expf(2.f * v.w - rm.w - cm) * ri.w * ci;
    attn[id] = v;
}

// ---------------------------------------------------------------------------
// vcatT[bh][d][n] = v[bh][n][d]  (32x32 smem transpose)
// ---------------------------------------------------------------------------
__global__ void build_vcatT(const float* __restrict__ qkvP, float* __restrict__ vcatT)
{
    __shared__ float t[32][33];
    const int bh = blockIdx.z;
    const int n0 = blockIdx.x * 32;
    const int d0 = blockIdx.y * 32;
    const float* src = qkvP + ((long long)(2 * BHN + bh) * SEQ) * HDIM;
    float* dst = vcatT + (long long)bh * DD * SEQ;
#pragma unroll
    for (int k = 0; k < 4; k++) {
        int n = n0 + threadIdx.y + k * 8;
        t[threadIdx.y + k * 8][threadIdx.x] = src[(long long)n * HDIM + d0 + threadIdx.x];
    }
    __syncthreads();
#pragma unroll
    for (int k = 0; k < 4; k++) {
        int d = d0 + threadIdx.y + k * 8;
        dst[(long long)d * SEQ + n0 + threadIdx.x] = t[threadIdx.x][threadIdx.y + k * 8];
    }
}

// positional rows e = 256..261 of vcatT
__global__ void build_pos(float* __restrict__ vcatT)
{
    const int n  = blockIdx.x * 256 + threadIdx.x;
    const int bh = blockIdx.y;
    int iy = n % 48;
    int ix = n / 48;
    float y = -1.f + 2.f * (float)iy / 47.f;
    float x = -1.f + 2.f * (float)ix / 63.f;
    float* dst = vcatT + (long long)bh * DD * SEQ + n;
    dst[(long long)(HDIM + 0) * SEQ] = y * y;
    dst[(long long)(HDIM + 1) * SEQ] = x * x;
    dst[(long long)(HDIM + 2) * SEQ] = y * x;
    dst[(long long)(HDIM + 3) * SEQ] = y;
    dst[(long long)(HDIM + 4) * SEQ] = x;
    dst[(long long)(HDIM + 5) * SEQ] = 1.f;
}

// ---------------------------------------------------------------------------
// fundT[b][e][h*DD+d] = fund[bh][d][e]
// ---------------------------------------------------------------------------
__global__ void transpose_fund(const float* __restrict__ fund, float* __restrict__ fundT)
{
    const long long idx = (long long)blockIdx.x * blockDim.x + threadIdx.x;
    if (idx >= (long long)BHN * DD * DD) return;
    const int e  = (int)(idx % DD);
    const long long r = idx / DD;
    const int d  = (int)(r % DD);
    const int bh = (int)(r / DD);
    const int b  = bh / NH;
    const int h  = bh - b * NH;
    fundT[((long long)b * DD + e) * HD3 + h * DD + d] = fund[idx];
}

// ---------------------------------------------------------------------------
// Launch
// ---------------------------------------------------------------------------
extern "C" void kernel_launch(void* const* d_in, const int* in_sizes, int n_in,
                              void* d_out, int out_size)
{
    const float* x    = (const float*)d_in[0];  // [4,3072,768]
    const float* Wqkv = (const float*)d_in[1];  // [2304,768]
    const float* Wpf  = (const float*)d_in[2];  // [768,786]
    const float* bpf  = (const float*)d_in[3];  // [768]
    float* out = (float*)d_out;                 // [4,262,768]

    float *qkvP, *attn, *vcatT, *f1, *fund, *fundT;
    float *rmax, *rinv, *cmax, *cinv, *pmax, *psum;
    cudaGetSymbolAddress((void**)&qkvP,  g_qkvP);
    cudaGetSymbolAddress((void**)&attn,  g_attn);
    cudaGetSymbolAddress((void**)&vcatT, g_vcatT);
    cudaGetSymbolAddress((void**)&f1,    g_f1);
    cudaGetSymbolAddress((void**)&fund,  g_fund);
    cudaGetSymbolAddress((void**)&fundT, g_fundT);
    cudaGetSymbolAddress((void**)&rmax,  g_rmax);
    cudaGetSymbolAddress((void**)&rinv,  g_rinv);
    cudaGetSymbolAddress((void**)&cmax,  g_cmax);
    cudaGetSymbolAddress((void**)&cinv,  g_cinv);
    cudaGetSymbolAddress((void**)&pmax,  g_pmax);
    cudaGetSymbolAddress((void**)&psum,  g_psum);

    cudaFuncSetAttribute(mma_gemm<0>, cudaFuncAttributeMaxDynamicSharedMemorySize, SMEM_TOTAL);
    cudaFuncSetAttribute(mma_gemm<1>, cudaFuncAttributeMaxDynamicSharedMemorySize, SMEM_TOTAL);
    cudaFuncSetAttribute(mma_gemm<2>, cudaFuncAttributeMaxDynamicSharedMemorySize, SMEM_TOTAL);

    const long long sQ = (long long)SEQ * HDIM;

    // 1) QKV projection, scattered to [s][bh][n][d]
    mma_gemm<1><<<dim3((3 * DIMC) / 128, (BB * SEQ) / 128, 1), 256, SMEM_TOTAL>>>(
        x, Wqkv, qkvP, nullptr,
        BB * SEQ, 3 * DIMC, DIMC, DIMC, DIMC, 0, 0, 0, 0, 1.f);

    // 2) attnT[m][n] = scale * k_m . q_n
    mma_gemm<0><<<dim3(SEQ / 128, SEQ / 128, BHN), 256, SMEM_TOTAL>>>(
        qkvP + (long long)BHN * sQ, qkvP, attn, nullptr,
        SEQ, SEQ, HDIM, HDIM, HDIM, SEQ,
        sQ, sQ, (long long)SEQ * SEQ, 0.0625f);

    // 3) stats: contiguous rows of attnT (per m) -> cmax/cinv; strided -> rmax/rinv
    row_stats<<<BHN * SEQ, 256>>>(attn, cmax, cinv);
    col_stats_part<<<dim3(SEQ / 128, BHN, NSP), 128>>>(attn, pmax, psum);
    col_stats_comb<<<(BHN * SEQ + 255) / 256, 256>>>(pmax, psum, rmax, rinv);

    // 4) attn_f^T in place (fp32)
    apply_softmax<<<(unsigned)(((long long)BHN * SEQ * SEQ / 4 + 255) / 256), 256>>>(
        (float4*)attn, rmax, rinv, cmax, cinv);

    // 5) vcatT = [v; pos]^T
    build_vcatT<<<dim3(SEQ / 32, HDIM / 32, BHN), dim3(32, 8)>>>(qkvP, vcatT);
    build_pos<<<dim3(SEQ / 256, BHN), 256>>>(vcatT);

    // 6) f1[d][m] = sum_n vcatT[d][n] * attn_fT[m][n]
    mma_gemm<0><<<dim3(SEQ / 128, (DD + 127) / 128, BHN), 256, SMEM_TOTAL>>>(
        vcatT, attn, f1, nullptr,
        DD, SEQ, SEQ, SEQ, SEQ, SEQ,
        (long long)DD * SEQ, (long long)SEQ * SEQ, (long long)DD * SEQ, 1.f);

    // 7) fund[d][e] = sum_m f1[d][m] * vcatT[e][m]
    mma_gemm<0><<<dim3((DD + 127) / 128, (DD + 127) / 128, BHN), 256, SMEM_TOTAL>>>(
        f1, vcatT, fund, nullptr,
        DD, DD, SEQ, SEQ, SEQ, DD,
        (long long)DD * SEQ, (long long)DD * SEQ, (long long)DD * DD, 1.f);

    // 8) reshape/transpose
    transpose_fund<<<(int)(((long long)BHN * DD * DD + 255) / 256), 256>>>(fund, fundT);

    // 9) out[b][e][o] = sum_j fundT[b][e][j] * Wpf[o][j] + bpf[o]
    mma_gemm<2><<<dim3(DIMC / 128, (DD + 127) / 128, BB), 256, SMEM_TOTAL>>>(
        fundT, Wpf, out, bpf,
        DD, DIMC, HD3, HD3, HD3, DIMC,
        (long long)DD * HD3, 0, (long long)DD * DIMC, 1.f);
}

// round 9
// speedup vs baseline: 4.6739x; 1.2658x over previous
#include <cuda_runtime.h>
#include <math.h>
#include <cstdint>

// ---------------------------------------------------------------------------
// Problem constants
// ---------------------------------------------------------------------------
#define BB    4
#define SEQ   3072
#define DIMC  768
#define NH    3
#define HDIM  256
#define DD    262
#define BHN   12
#define HD3   786
#define HD3P  788          // padded to 16B-aligned rows
#define NSP   32

// ---------------------------------------------------------------------------
// Scratch (device globals: sanctioned alloc-free scratch)
// ---------------------------------------------------------------------------
static __device__ float g_qkvP[(size_t)3 * BHN * SEQ * HDIM];  // [s][bh][n][d] (tf32-rounded)
static __device__ float g_attn[(size_t)BHN * SEQ * SEQ];       // attnT: [bh][m][n]
static __device__ float g_vcatT[(size_t)BHN * DD * SEQ];       // [bh][e][n] (rounded)
static __device__ float g_f1  [(size_t)BHN * DD * SEQ];        // [bh][d][m] (rounded)
static __device__ float g_fund[(size_t)BHN * DD * DD];
static __device__ float g_fundT[(size_t)BB * DD * HD3P];       // padded ld (rounded)
static __device__ float g_xr[(size_t)BB * SEQ * DIMC];         // rounded x
static __device__ float g_wqkvr[(size_t)3 * DIMC * DIMC];      // rounded W_qkv
static __device__ float g_wpfr[(size_t)DIMC * HD3P];           // rounded+padded W_pf
static __device__ float g_rmax[BHN * SEQ], g_rinv[BHN * SEQ];
static __device__ float g_cmax[BHN * SEQ], g_cinv[BHN * SEQ];
static __device__ float g_pmax[NSP * BHN * SEQ], g_psum[NSP * BHN * SEQ];

// ---------------------------------------------------------------------------
// Helpers (plain sm_80-era PTX; nothing "a"-gated)
// ---------------------------------------------------------------------------
__device__ __forceinline__ uint32_t smem_u32(const void* p) {
    uint32_t a;
    asm("{ .reg .u64 t; cvta.to.shared.u64 t, %1; cvt.u32.u64 %0, t; }" : "=r"(a) : "l"(p));
    return a;
}
__device__ __forceinline__ float cvt_tf32(float x) {
    float y; asm("cvt.rna.tf32.f32 %0, %1;" : "=f"(y) : "f"(x)); return y;
}
__device__ __forceinline__ void cp16(uint32_t dst, const void* src, int srcbytes) {
    asm volatile("cp.async.cg.shared.global [%0], [%1], 16, %2;"
                 :: "r"(dst), "l"(src), "r"(srcbytes));
}
__device__ __forceinline__ void cp_commit() { asm volatile("cp.async.commit_group;"); }
__device__ __forceinline__ void cp_wait1()  { asm volatile("cp.async.wait_group 1;"); }
__device__ __forceinline__ void cp_wait0()  { asm volatile("cp.async.wait_group 0;"); }

#define LDSM_X4(r, addr) \
    asm volatile("ldmatrix.sync.aligned.m8n8.x4.shared.b16 {%0,%1,%2,%3}, [%4];" \
        : "=r"((r)[0]), "=r"((r)[1]), "=r"((r)[2]), "=r"((r)[3]) : "r"(addr))

#define MMA_TF32(c, a, b0v, b1v) \
    asm volatile("mma.sync.aligned.m16n8k8.row.col.f32.tf32.tf32.f32 " \
        "{%0,%1,%2,%3}, {%4,%5,%6,%7}, {%8,%9}, {%0,%1,%2,%3};" \
        : "+f"((c)[0]), "+f"((c)[1]), "+f"((c)[2]), "+f"((c)[3]) \
        : "r"((a)[0]), "r"((a)[1]), "r"((a)[2]), "r"((a)[3]), "r"(b0v), "r"(b1v))

// ---------------------------------------------------------------------------
// tf32 tensor-core GEMM, cp.async 3-stage pipeline.
// C[i,j] = alpha * sum_k A(i,k)*B(j,k); operands PRE-ROUNDED to tf32 in gmem.
// CTA tile 128x128, K-tile 32, 256 threads (8 warps, 64Mx32N warptile).
// EPI 0: plain store; EPI 1: QKV scatter; EPI 2: +bias[j]. RND: tf32-round output.
// ---------------------------------------------------------------------------
#define STAGE_STRIDE 32768u
static constexpr unsigned SMEM_TOTAL = 3 * STAGE_STRIDE;   // 96 KB

__device__ __forceinline__ void issue_stage(
    const float* __restrict__ A, const float* __restrict__ B, uint32_t sb, int kt,
    int i0, int j0, int M, int N, int K, int lda, int ldb, int u, int rs)
{
    const uint32_t aB = sb + (uint32_t)(kt % 3) * STAGE_STRIDE;
    const uint32_t bB = aB + 16384u;
    const int kk  = kt * 32 + u * 4;
    const int rem = K - kk;
    const int bytes = rem >= 4 ? 16 : (rem > 0 ? rem * 4 : 0);
    const uint32_t csw = (uint32_t)(u * 16);
#pragma unroll
    for (int it = 0; it < 4; it++) {
        int r = rs + it * 32;
        uint32_t off = (uint32_t)(r * 128) + (csw ^ (uint32_t)((r & 7) << 4));
        int gia = i0 + r, gib = j0 + r;
        const float* pa = A + (long long)(gia < M ? gia : 0) * lda + kk;
        const float* pb = B + (long long)(gib < N ? gib : 0) * ldb + kk;
        cp16(aB + off, pa, gia < M ? bytes : 0);
        cp16(bB + off, pb, gib < N ? bytes : 0);
    }
    cp_commit();
}

template<int EPI, int RND>
__global__ void __launch_bounds__(256, 2) ca_gemm(
    const float* __restrict__ A, const float* __restrict__ B,
    float* __restrict__ C, const float* __restrict__ bias,
    int M, int N, int K, int lda, int ldb, int ldc,
    long long sA, long long sB, long long sC, float alpha)
{
    extern __shared__ char smem[];
    const uint32_t sb = smem_u32(smem);

    A += (long long)blockIdx.z * sA;
    B += (long long)blockIdx.z * sB;
    if (EPI != 1) C += (long long)blockIdx.z * sC;
    const int i0 = blockIdx.y * 128;
    const int j0 = blockIdx.x * 128;

    const int tid  = threadIdx.x;
    const int wid  = tid >> 5, lane = tid & 31;
    const int wm   = wid >> 2, wn = wid & 3;
    const int g    = lane >> 2, tg = lane & 3;
    const int sub  = lane >> 3, l  = lane & 7;
    const int u    = tid & 7,  rs  = tid >> 3;

    const int halfA = sub >> 1;
    const int halfB = sub & 1;
    uint32_t laOff[4], la7[4], lbOff[2], lb7[2];
#pragma unroll
    for (int m = 0; m < 4; m++) {
        int r = wm * 64 + m * 16 + (sub & 1) * 8 + l;
        laOff[m] = (uint32_t)(r * 128); la7[m] = (uint32_t)(r & 7);
    }
#pragma unroll
    for (int p = 0; p < 2; p++) {
        int r = wn * 32 + p * 16 + (sub >> 1) * 8 + l;
        lbOff[p] = (uint32_t)(r * 128); lb7[p] = (uint32_t)(r & 7);
    }

    float acc[4][4][4];
#pragma unroll
    for (int m = 0; m < 4; m++)
#pragma unroll
        for (int n = 0; n < 4; n++)
#pragma unroll
            for (int e = 0; e < 4; e++) acc[m][n][e] = 0.f;

    const int nk = (K + 31) / 32;
    issue_stage(A, B, sb, 0, i0, j0, M, N, K, lda, ldb, u, rs);
    if (nk > 1) issue_stage(A, B, sb, 1, i0, j0, M, N, K, lda, ldb, u, rs);

    for (int kt = 0; kt < nk; kt++) {
        if (kt + 1 < nk) cp_wait1(); else cp_wait0();
        __syncthreads();
        if (kt + 2 < nk)
            issue_stage(A, B, sb, kt + 2, i0, j0, M, N, K, lda, ldb, u, rs);

        const uint32_t aB = sb + (uint32_t)(kt % 3) * STAGE_STRIDE;
        const uint32_t bB = aB + 16384u;
#pragma unroll
        for (int ks = 0; ks < 4; ks++) {
            uint32_t af[4][4], bf[2][4];
#pragma unroll
            for (int m = 0; m < 4; m++) {
                uint32_t ch = (uint32_t)(ks * 2 + halfA) ^ la7[m];
                LDSM_X4(af[m], aB + laOff[m] + (ch << 4));
            }
#pragma unroll
            for (int p = 0; p < 2; p++) {
                uint32_t ch = (uint32_t)(ks * 2 + halfB) ^ lb7[p];
                LDSM_X4(bf[p], bB + lbOff[p] + (ch << 4));
            }
#pragma unroll
            for (int m = 0; m < 4; m++) {
#pragma unroll
                for (int n = 0; n < 4; n++)
                    MMA_TF32(acc[m][n], af[m], bf[n >> 1][(n & 1) * 2], bf[n >> 1][(n & 1) * 2 + 1]);
            }
        }
        // next iteration's __syncthreads (after its wait) protects buffer reuse
    }

    // ---- epilogue: direct reg -> gmem (v2 stores) ----
#pragma unroll
    for (int m = 0; m < 4; m++) {
        int r0 = i0 + wm * 64 + m * 16 + g;
#pragma unroll
        for (int n = 0; n < 4; n++) {
            int gj = j0 + wn * 32 + n * 8 + 2 * tg;
            if (gj >= N) continue;
            float2 v0 = make_float2(acc[m][n][0] * alpha, acc[m][n][1] * alpha);
            float2 v1 = make_float2(acc[m][n][2] * alpha, acc[m][n][3] * alpha);
            if (EPI == 2) {
                float2 bv = *(const float2*)(bias + gj);
                v0.x += bv.x; v0.y += bv.y; v1.x += bv.x; v1.y += bv.y;
            }
            if (RND) {
                v0.x = cvt_tf32(v0.x); v0.y = cvt_tf32(v0.y);
                v1.x = cvt_tf32(v1.x); v1.y = cvt_tf32(v1.y);
            }
            if (EPI == 1) {
                int s_  = gj / DIMC;
                int rc  = gj - s_ * DIMC;
                int h   = rc >> 8;
                int d   = rc & 255;
#pragma unroll
                for (int hh = 0; hh < 2; hh++) {
                    int gi = r0 + hh * 8;
                    if (gi >= M) continue;
                    int b_ = gi / SEQ, nn = gi - b_ * SEQ;
                    long long dst = ((((long long)s_ * BHN) + (b_ * NH + h)) * SEQ + nn) * HDIM + d;
                    *(float2*)&C[dst] = hh ? v1 : v0;
                }
            } else {
                if (r0 < M)     *(float2*)&C[(long long)r0 * ldc + gj] = v0;
                if (r0 + 8 < M) *(float2*)&C[(long long)(r0 + 8) * ldc + gj] = v1;
            }
        }
    }
}

// ---------------------------------------------------------------------------
// Prep: tf32-round copies of external inputs
// ---------------------------------------------------------------------------
__global__ void round_copy4(const float4* __restrict__ src, float4* __restrict__ dst, int n4)
{
    int i = blockIdx.x * 256 + threadIdx.x;
    if (i >= n4) return;
    float4 v = src[i];
    v.x = cvt_tf32(v.x); v.y = cvt_tf32(v.y); v.z = cvt_tf32(v.z); v.w = cvt_tf32(v.w);
    dst[i] = v;
}

__global__ void pad_round_wpf(const float* __restrict__ W, float* __restrict__ out)
{
    int idx = blockIdx.x * 256 + threadIdx.x;
    if (idx >= DIMC * HD3P) return;
    int o = idx / HD3P, j = idx - o * HD3P;
    out[idx] = (j < HD3) ? cvt_tf32(W[o * HD3 + j]) : 0.f;
}

// ---------------------------------------------------------------------------
// Softmax stats on attnT[m][n].
// ---------------------------------------------------------------------------
__global__ void row_stats(const float* __restrict__ attn,
                          float* __restrict__ omax, float* __restrict__ oinv)
{
    __shared__ float sm[256];
    const long long row = blockIdx.x;
    const float4* a = (const float4*)(attn + row * SEQ);
    const int t = threadIdx.x;

    float4 v[3];
#pragma unroll
    for (int u = 0; u < 3; u++) v[u] = a[t + 256 * u];

    float m = -INFINITY;
#pragma unroll
    for (int u = 0; u < 3; u++)
        m = fmaxf(m, fmaxf(fmaxf(v[u].x, v[u].y), fmaxf(v[u].z, v[u].w)));
    sm[t] = m; __syncthreads();
    for (int off = 128; off > 0; off >>= 1) {
        if (t < off) sm[t] = fmaxf(sm[t], sm[t + off]);
        __syncthreads();
    }
    const float M = sm[0]; __syncthreads();

    float s = 0.f;
#pragma unroll
    for (int u = 0; u < 3; u++)
        s += __expf(v[u].x - M) + __expf(v[u].y - M) + __expf(v[u].z - M) + __expf(v[u].w - M);
    sm[t] = s; __syncthreads();
    for (int off = 128; off > 0; off >>= 1) {
        if (t < off) sm[t] += sm[t + off];
        __syncthreads();
    }
    if (t == 0) { omax[row] = M; oinv[row] = 1.f / sm[0]; }
}

// 4 adjacent columns per thread via float4 (coalesced 512B/warp requests)
__global__ void col_stats_part(const float* __restrict__ attn,
                               float* __restrict__ pmax, float* __restrict__ psum)
{
    const int bh = blockIdx.y;
    const int sp = blockIdx.z;
    const int n0 = blockIdx.x * 512 + threadIdx.x * 4;
    const float* a = attn + (long long)bh * SEQ * SEQ
                          + (long long)(sp * (SEQ / NSP)) * SEQ + n0;

    float mx[4] = {-INFINITY, -INFINITY, -INFINITY, -INFINITY};
    float ss[4] = {0.f, 0.f, 0.f, 0.f};
#pragma unroll 4
    for (int m = 0; m < SEQ / NSP; m++) {
        float4 v4 = *(const float4*)(a + (long long)m * SEQ);
        float vv[4] = {v4.x, v4.y, v4.z, v4.w};
#pragma unroll
        for (int q = 0; q < 4; q++) {
            float v = vv[q];
            if (v <= mx[q]) {
                ss[q] += __expf(v - mx[q]);
            } else {
                ss[q] = ss[q] * __expf(mx[q] - v) + 1.f;
                mx[q] = v;
            }
        }
    }
    long long base = (long long)sp * (BHN * SEQ) + bh * SEQ + n0;
    *(float4*)&pmax[base] = make_float4(mx[0], mx[1], mx[2], mx[3]);
    *(float4*)&psum[base] = make_float4(ss[0], ss[1], ss[2], ss[3]);
}

__global__ void col_stats_comb(const float* __restrict__ pmax, const float* __restrict__ psum,
                               float* __restrict__ omax, float* __restrict__ oinv)
{
    const int idx = blockIdx.x * 256 + threadIdx.x;
    if (idx >= BHN * SEQ) return;
    float M = -INFINITY;
#pragma unroll
    for (int sp = 0; sp < NSP; sp++) M = fmaxf(M, pmax[sp * (BHN * SEQ) + idx]);
    float S = 0.f;
#pragma unroll
    for (int sp = 0; sp < NSP; sp++)
        S += psum[sp * (BHN * SEQ) + idx] * __expf(pmax[sp * (BHN * SEQ) + idx] - M);
    omax[idx] = M;
    oinv[idx] = 1.f / S;
}

// ---------------------------------------------------------------------------
// attn_f^T[m][n] = exp(2a - rmax[n] - cmax[m]) * rinv[n] * cinv[m]
// written tf32-rounded in place (feeds the f1 GEMM via cp.async)
// ---------------------------------------------------------------------------
__global__ void apply_softmax(float4* __restrict__ attn,
                              const float* __restrict__ rmax, const float* __restrict__ rinv,
                              const float* __restrict__ cmax, const float* __restrict__ cinv)
{
    const long long id = (long long)blockIdx.x * blockDim.x + threadIdx.x;
    if (id >= (long long)BHN * SEQ * SEQ / 4) return;
    const long long base = id * 4;
    const int n0 = (int)(base % SEQ);
    const long long rg = base / SEQ;        // bh*SEQ + m
    const int bh = (int)(rg / SEQ);

    const float cm = cmax[rg];
    const float ci = cinv[rg];
    const float4 rm = *(const float4*)(rmax + (long long)bh * SEQ + n0);
    const float4 ri = *(const float4*)(rinv + (long long)bh * SEQ + n0);

    float4 v = attn[id];
    v.x = cvt_tf32(__expf(2.f * v.x - rm.x - cm) * ri.x * ci);
    v.y = cvt_tf32(__expf(2.f * v.y - rm.y - cm) * ri.y * ci);
    v.z = cvt_tf32(__expf(2.f * v.z - rm.z - cm) * ri.z * ci);
    v.w = cvt_tf32(__expf(2.f * v.w - rm.w - cm) * ri.w * ci);
    attn[id] = v;
}

// ---------------------------------------------------------------------------
// vcatT[bh][d][n] = v[bh][n][d]  (32x32 smem transpose, rounded)
// ---------------------------------------------------------------------------
__global__ void build_vcatT(const float* __restrict__ qkvP, float* __restrict__ vcatT)
{
    __shared__ float t[32][33];
    const int bh = blockIdx.z;
    const int n0 = blockIdx.x * 32;
    const int d0 = blockIdx.y * 32;
    const float* src = qkvP + ((long long)(2 * BHN + bh) * SEQ) * HDIM;
    float* dst = vcatT + (long long)bh * DD * SEQ;
#pragma unroll
    for (int k = 0; k < 4; k++) {
        int n = n0 + threadIdx.y + k * 8;
        t[threadIdx.y + k * 8][threadIdx.x] = src[(long long)n * HDIM + d0 + threadIdx.x];
    }
    __syncthreads();
#pragma unroll
    for (int k = 0; k < 4; k++) {
        int d = d0 + threadIdx.y + k * 8;
        dst[(long long)d * SEQ + n0 + threadIdx.x] = t[threadIdx.x][threadIdx.y + k * 8];
    }
}

__global__ void build_pos(float* __restrict__ vcatT)
{
    const int n  = blockIdx.x * 256 + threadIdx.x;
    const int bh = blockIdx.y;
    int iy = n % 48;
    int ix = n / 48;
    float y = -1.f + 2.f * (float)iy / 47.f;
    float x = -1.f + 2.f * (float)ix / 63.f;
    float* dst = vcatT + (long long)bh * DD * SEQ + n;
    dst[(long long)(HDIM + 0) * SEQ] = cvt_tf32(y * y);
    dst[(long long)(HDIM + 1) * SEQ] = cvt_tf32(x * x);
    dst[(long long)(HDIM + 2) * SEQ] = cvt_tf32(y * x);
    dst[(long long)(HDIM + 3) * SEQ] = cvt_tf32(y);
    dst[(long long)(HDIM + 4) * SEQ] = cvt_tf32(x);
    dst[(long long)(HDIM + 5) * SEQ] = 1.f;
}

// ---------------------------------------------------------------------------
// fundT[b][e][h*DD+d] = fund[bh][d][e]  (rounded, padded ld)
// ---------------------------------------------------------------------------
__global__ void transpose_fund(const float* __restrict__ fund, float* __restrict__ fundT)
{
    const long long idx = (long long)blockIdx.x * blockDim.x + threadIdx.x;
    if (idx >= (long long)BHN * DD * DD) return;
    const int e  = (int)(idx % DD);
    const long long r = idx / DD;
    const int d  = (int)(r % DD);
    const int bh = (int)(r / DD);
    const int b  = bh / NH;
    const int h  = bh - b * NH;
    fundT[((long long)b * DD + e) * HD3P + h * DD + d] = cvt_tf32(fund[idx]);
}

__global__ void zero_pad_fundT(float* __restrict__ fundT)
{
    const int idx = blockIdx.x * 256 + threadIdx.x;
    if (idx >= BB * DD * 2) return;
    int p = idx & 1, row = idx >> 1;
    fundT[(long long)row * HD3P + HD3 + p] = 0.f;
}

// ---------------------------------------------------------------------------
// Launch
// ---------------------------------------------------------------------------
extern "C" void kernel_launch(void* const* d_in, const int* in_sizes, int n_in,
                              void* d_out, int out_size)
{
    const float* x    = (const float*)d_in[0];  // [4,3072,768]
    const float* Wqkv = (const float*)d_in[1];  // [2304,768]
    const float* Wpf  = (const float*)d_in[2];  // [768,786]
    const float* bpf  = (const float*)d_in[3];  // [768]
    float* out = (float*)d_out;                 // [4,262,768]

    float *qkvP, *attn, *vcatT, *f1, *fund, *fundT, *xr, *wqkvr, *wpfr;
    float *rmax, *rinv, *cmax, *cinv, *pmax, *psum;
    cudaGetSymbolAddress((void**)&qkvP,  g_qkvP);
    cudaGetSymbolAddress((void**)&attn,  g_attn);
    cudaGetSymbolAddress((void**)&vcatT, g_vcatT);
    cudaGetSymbolAddress((void**)&f1,    g_f1);
    cudaGetSymbolAddress((void**)&fund,  g_fund);
    cudaGetSymbolAddress((void**)&fundT, g_fundT);
    cudaGetSymbolAddress((void**)&xr,    g_xr);
    cudaGetSymbolAddress((void**)&wqkvr, g_wqkvr);
    cudaGetSymbolAddress((void**)&wpfr,  g_wpfr);
    cudaGetSymbolAddress((void**)&rmax,  g_rmax);
    cudaGetSymbolAddress((void**)&rinv,  g_rinv);
    cudaGetSymbolAddress((void**)&cmax,  g_cmax);
    cudaGetSymbolAddress((void**)&cinv,  g_cinv);
    cudaGetSymbolAddress((void**)&pmax,  g_pmax);
    cudaGetSymbolAddress((void**)&psum,  g_psum);

    cudaFuncSetAttribute(ca_gemm<0,0>, cudaFuncAttributeMaxDynamicSharedMemorySize, SMEM_TOTAL);
    cudaFuncSetAttribute(ca_gemm<0,1>, cudaFuncAttributeMaxDynamicSharedMemorySize, SMEM_TOTAL);
    cudaFuncSetAttribute(ca_gemm<1,1>, cudaFuncAttributeMaxDynamicSharedMemorySize, SMEM_TOTAL);
    cudaFuncSetAttribute(ca_gemm<2,0>, cudaFuncAttributeMaxDynamicSharedMemorySize, SMEM_TOTAL);

    const long long sQ = (long long)SEQ * HDIM;

    // 0) tf32-round external operands
    round_copy4<<<(BB * SEQ * DIMC / 4 + 255) / 256, 256>>>(
        (const float4*)x, (float4*)xr, BB * SEQ * DIMC / 4);
    round_copy4<<<(3 * DIMC * DIMC / 4 + 255) / 256, 256>>>(
        (const float4*)Wqkv, (float4*)wqkvr, 3 * DIMC * DIMC / 4);
    pad_round_wpf<<<(DIMC * HD3P + 255) / 256, 256>>>(Wpf, wpfr);

    // 1) QKV projection, scattered (rounded) to [s][bh][n][d]
    ca_gemm<1,1><<<dim3((3 * DIMC) / 128, (BB * SEQ) / 128, 1), 256, SMEM_TOTAL>>>(
        xr, wqkvr, qkvP, nullptr,
        BB * SEQ, 3 * DIMC, DIMC, DIMC, DIMC, 0, 0, 0, 0, 1.f);

    // 2) attnT[m][n] = scale * k_m . q_n  (fp32 logits, NOT rounded)
    ca_gemm<0,0><<<dim3(SEQ / 128, SEQ / 128, BHN), 256, SMEM_TOTAL>>>(
        qkvP + (long long)BHN * sQ, qkvP, attn, nullptr,
        SEQ, SEQ, HDIM, HDIM, HDIM, SEQ,
        sQ, sQ, (long long)SEQ * SEQ, 0.0625f);

    // 3) stats
    row_stats<<<BHN * SEQ, 256>>>(attn, cmax, cinv);
    col_stats_part<<<dim3(SEQ / 512, BHN, NSP), 128>>>(attn, pmax, psum);
    col_stats_comb<<<(BHN * SEQ + 255) / 256, 256>>>(pmax, psum, rmax, rinv);

    // 4) attn_f^T in place (tf32-rounded)
    apply_softmax<<<(unsigned)(((long long)BHN * SEQ * SEQ / 4 + 255) / 256), 256>>>(
        (float4*)attn, rmax, rinv, cmax, cinv);

    // 5) vcatT = [v; pos]^T (rounded)
    build_vcatT<<<dim3(SEQ / 32, HDIM / 32, BHN), dim3(32, 8)>>>(qkvP, vcatT);
    build_pos<<<dim3(SEQ / 256, BHN), 256>>>(vcatT);

    // 6) f1[d][m] = sum_n vcatT[d][n] * attn_fT[m][n]  (rounded out)
    ca_gemm<0,1><<<dim3(SEQ / 128, (DD + 127) / 128, BHN), 256, SMEM_TOTAL>>>(
        vcatT, attn, f1, nullptr,
        DD, SEQ, SEQ, SEQ, SEQ, SEQ,
        (long long)DD * SEQ, (long long)SEQ * SEQ, (long long)DD * SEQ, 1.f);

    // 7) fund[d][e] = sum_m f1[d][m] * vcatT[e][m]
    ca_gemm<0,0><<<dim3((DD + 127) / 128, (DD + 127) / 128, BHN), 256, SMEM_TOTAL>>>(
        f1, vcatT, fund, nullptr,
        DD, DD, SEQ, SEQ, SEQ, DD,
        (long long)DD * SEQ, (long long)DD * SEQ, (long long)DD * DD, 1.f);

    // 8) reshape/transpose (rounded, padded)
    transpose_fund<<<(int)(((long long)BHN * DD * DD + 255) / 256), 256>>>(fund, fundT);
    zero_pad_fundT<<<(BB * DD * 2 + 255) / 256, 256>>>(fundT);

    // 9) out[b][e][o] = sum_j fundT[b][e][j] * Wpf[o][j] + bpf[o]
    ca_gemm<2,0><<<dim3(DIMC / 128, (DD + 127) / 128, BB), 256, SMEM_TOTAL>>>(
        fundT, wpfr, out, bpf,
        DD, DIMC, HD3, HD3P, HD3P, DIMC,
        (long long)DD * HD3P, 0, (long long)DD * DIMC, 1.f);
}

// round 10
// speedup vs baseline: 5.2697x; 1.1275x over previous
#include <cuda_runtime.h>
#include <math.h>
#include <cstdint>

// ---------------------------------------------------------------------------
// Problem constants
// ---------------------------------------------------------------------------
#define BB    4
#define SEQ   3072
#define DIMC  768
#define NH    3
#define HDIM  256
#define DD    262
#define BHN   12
#define HD3   786
#define HD3P  788          // padded to 16B-aligned rows
#define NPART (SEQ / 128)  // 24 partial sums per row/col

// ---------------------------------------------------------------------------
// Scratch (device globals: sanctioned alloc-free scratch)
// ---------------------------------------------------------------------------
static __device__ float g_qkvP[(size_t)3 * BHN * SEQ * HDIM];  // [s][bh][n][d] (tf32-rounded)
static __device__ float g_attn[(size_t)BHN * SEQ * SEQ];       // attnT: [bh][m][n] (e, then attn_f)
static __device__ float g_vcatT[(size_t)BHN * DD * SEQ];       // [bh][e][n] (rounded)
static __device__ float g_f1  [(size_t)BHN * DD * SEQ];        // [bh][d][m] (rounded)
static __device__ float g_fund[(size_t)BHN * DD * DD];
static __device__ float g_fundT[(size_t)BB * DD * HD3P];       // padded ld (rounded)
static __device__ float g_xr[(size_t)BB * SEQ * DIMC];         // rounded x
static __device__ float g_wqkvr[(size_t)3 * DIMC * DIMC];      // rounded W_qkv
static __device__ float g_wpfr[(size_t)DIMC * HD3P];           // rounded+padded W_pf
static __device__ float g_rinv[BHN * SEQ];                     // 1/col-sum (per n)
static __device__ float g_cinv[BHN * SEQ];                     // 1/row-sum (per m)
static __device__ float g_csump[(size_t)NPART * BHN * SEQ];    // partial row-sums (per m)
static __device__ float g_rsump[(size_t)NPART * BHN * SEQ];    // partial col-sums (per n)

// ---------------------------------------------------------------------------
// Helpers (plain sm_80-era PTX; nothing "a"-gated)
// ---------------------------------------------------------------------------
__device__ __forceinline__ uint32_t smem_u32(const void* p) {
    uint32_t a;
    asm("{ .reg .u64 t; cvta.to.shared.u64 t, %1; cvt.u32.u64 %0, t; }" : "=r"(a) : "l"(p));
    return a;
}
__device__ __forceinline__ float cvt_tf32(float x) {
    float y; asm("cvt.rna.tf32.f32 %0, %1;" : "=f"(y) : "f"(x)); return y;
}
__device__ __forceinline__ void cp16(uint32_t dst, const void* src, int srcbytes) {
    asm volatile("cp.async.cg.shared.global [%0], [%1], 16, %2;"
                 :: "r"(dst), "l"(src), "r"(srcbytes));
}
__device__ __forceinline__ void cp_commit() { asm volatile("cp.async.commit_group;"); }
__device__ __forceinline__ void cp_wait1()  { asm volatile("cp.async.wait_group 1;"); }
__device__ __forceinline__ void cp_wait0()  { asm volatile("cp.async.wait_group 0;"); }

#define LDSM_X4(r, addr) \
    asm volatile("ldmatrix.sync.aligned.m8n8.x4.shared.b16 {%0,%1,%2,%3}, [%4];" \
        : "=r"((r)[0]), "=r"((r)[1]), "=r"((r)[2]), "=r"((r)[3]) : "r"(addr))

#define MMA_TF32(c, a, b0v, b1v) \
    asm volatile("mma.sync.aligned.m16n8k8.row.col.f32.tf32.tf32.f32 " \
        "{%0,%1,%2,%3}, {%4,%5,%6,%7}, {%8,%9}, {%0,%1,%2,%3};" \
        : "+f"((c)[0]), "+f"((c)[1]), "+f"((c)[2]), "+f"((c)[3]) \
        : "r"((a)[0]), "r"((a)[1]), "r"((a)[2]), "r"((a)[3]), "r"(b0v), "r"(b1v))

// ---------------------------------------------------------------------------
// tf32 tensor-core GEMM, cp.async 3-stage pipeline.
// C[i,j] = alpha * sum_k A(i,k)*B(j,k); operands PRE-ROUNDED to tf32 in gmem.
// CTA tile 128x128, K-tile 32, 256 threads (8 warps, 64Mx32N warptile).
// EPI 0: plain store; EPI 1: QKV scatter; EPI 2: +bias[j];
// EPI 3: store exp(v) + per-CTA row/col partial sums (softmax fusion).
// RND: tf32-round output.
// ---------------------------------------------------------------------------
#define STAGE_STRIDE 32768u
static constexpr unsigned SMEM_TOTAL = 3 * STAGE_STRIDE;   // 96 KB

__device__ __forceinline__ void issue_stage(
    const float* __restrict__ A, const float* __restrict__ B, uint32_t sb, int kt,
    int i0, int j0, int M, int N, int K, int lda, int ldb, int u, int rs)
{
    const uint32_t aB = sb + (uint32_t)(kt % 3) * STAGE_STRIDE;
    const uint32_t bB = aB + 16384u;
    const int kk  = kt * 32 + u * 4;
    const int rem = K - kk;
    const int bytes = rem >= 4 ? 16 : (rem > 0 ? rem * 4 : 0);
    const uint32_t csw = (uint32_t)(u * 16);
#pragma unroll
    for (int it = 0; it < 4; it++) {
        int r = rs + it * 32;
        uint32_t off = (uint32_t)(r * 128) + (csw ^ (uint32_t)((r & 7) << 4));
        int gia = i0 + r, gib = j0 + r;
        const float* pa = A + (long long)(gia < M ? gia : 0) * lda + kk;
        const float* pb = B + (long long)(gib < N ? gib : 0) * ldb + kk;
        cp16(aB + off, pa, gia < M ? bytes : 0);
        cp16(bB + off, pb, gib < N ? bytes : 0);
    }
    cp_commit();
}

template<int EPI, int RND>
__global__ void __launch_bounds__(256, 2) ca_gemm(
    const float* __restrict__ A, const float* __restrict__ B,
    float* __restrict__ C, const float* __restrict__ bias,
    int M, int N, int K, int lda, int ldb, int ldc,
    long long sA, long long sB, long long sC, float alpha,
    float* __restrict__ csump, float* __restrict__ rsump)
{
    extern __shared__ char smem[];
    const uint32_t sb = smem_u32(smem);

    A += (long long)blockIdx.z * sA;
    B += (long long)blockIdx.z * sB;
    if (EPI != 1) C += (long long)blockIdx.z * sC;
    const int i0 = blockIdx.y * 128;
    const int j0 = blockIdx.x * 128;

    const int tid  = threadIdx.x;
    const int wid  = tid >> 5, lane = tid & 31;
    const int wm   = wid >> 2, wn = wid & 3;
    const int g    = lane >> 2, tg = lane & 3;
    const int sub  = lane >> 3, l  = lane & 7;
    const int u    = tid & 7,  rs  = tid >> 3;

    const int halfA = sub >> 1;
    const int halfB = sub & 1;
    uint32_t laOff[4], la7[4], lbOff[2], lb7[2];
#pragma unroll
    for (int m = 0; m < 4; m++) {
        int r = wm * 64 + m * 16 + (sub & 1) * 8 + l;
        laOff[m] = (uint32_t)(r * 128); la7[m] = (uint32_t)(r & 7);
    }
#pragma unroll
    for (int p = 0; p < 2; p++) {
        int r = wn * 32 + p * 16 + (sub >> 1) * 8 + l;
        lbOff[p] = (uint32_t)(r * 128); lb7[p] = (uint32_t)(r & 7);
    }

    float acc[4][4][4];
#pragma unroll
    for (int m = 0; m < 4; m++)
#pragma unroll
        for (int n = 0; n < 4; n++)
#pragma unroll
            for (int e = 0; e < 4; e++) acc[m][n][e] = 0.f;

    const int nk = (K + 31) / 32;
    issue_stage(A, B, sb, 0, i0, j0, M, N, K, lda, ldb, u, rs);
    if (nk > 1) issue_stage(A, B, sb, 1, i0, j0, M, N, K, lda, ldb, u, rs);

    for (int kt = 0; kt < nk; kt++) {
        if (kt + 1 < nk) cp_wait1(); else cp_wait0();
        __syncthreads();
        if (kt + 2 < nk)
            issue_stage(A, B, sb, kt + 2, i0, j0, M, N, K, lda, ldb, u, rs);

        const uint32_t aB = sb + (uint32_t)(kt % 3) * STAGE_STRIDE;
        const uint32_t bB = aB + 16384u;
#pragma unroll
        for (int ks = 0; ks < 4; ks++) {
            uint32_t af[4][4], bf[2][4];
#pragma unroll
            for (int m = 0; m < 4; m++) {
                uint32_t ch = (uint32_t)(ks * 2 + halfA) ^ la7[m];
                LDSM_X4(af[m], aB + laOff[m] + (ch << 4));
            }
#pragma unroll
            for (int p = 0; p < 2; p++) {
                uint32_t ch = (uint32_t)(ks * 2 + halfB) ^ lb7[p];
                LDSM_X4(bf[p], bB + lbOff[p] + (ch << 4));
            }
#pragma unroll
            for (int m = 0; m < 4; m++) {
#pragma unroll
                for (int n = 0; n < 4; n++)
                    MMA_TF32(acc[m][n], af[m], bf[n >> 1][(n & 1) * 2], bf[n >> 1][(n & 1) * 2 + 1]);
            }
        }
    }

    if (EPI == 3) {
        // ---- softmax-fused epilogue: store e=exp(v*alpha), reduce partials ----
        __syncthreads();
        float* red = (float*)smem;            // [0:128) row sums, [128:256) col sums
        red[tid] = 0.f;
        __syncthreads();

        float colacc[4][2];
#pragma unroll
        for (int n = 0; n < 4; n++) { colacc[n][0] = 0.f; colacc[n][1] = 0.f; }

#pragma unroll
        for (int m = 0; m < 4; m++) {
            int r0 = i0 + wm * 64 + m * 16 + g;
            float rowacc0 = 0.f, rowacc1 = 0.f;
#pragma unroll
            for (int n = 0; n < 4; n++) {
                int gj = j0 + wn * 32 + n * 8 + 2 * tg;
                float e0 = __expf(acc[m][n][0] * alpha);
                float e1 = __expf(acc[m][n][1] * alpha);
                float e2 = __expf(acc[m][n][2] * alpha);
                float e3 = __expf(acc[m][n][3] * alpha);
                *(float2*)&C[(long long)r0 * ldc + gj]       = make_float2(e0, e1);
                *(float2*)&C[(long long)(r0 + 8) * ldc + gj] = make_float2(e2, e3);
                rowacc0 += e0 + e1; rowacc1 += e2 + e3;
                colacc[n][0] += e0 + e2; colacc[n][1] += e1 + e3;
            }
            // reduce row sums across tg (lane bits 0-1)
            rowacc0 += __shfl_xor_sync(0xffffffffu, rowacc0, 1);
            rowacc0 += __shfl_xor_sync(0xffffffffu, rowacc0, 2);
            rowacc1 += __shfl_xor_sync(0xffffffffu, rowacc1, 1);
            rowacc1 += __shfl_xor_sync(0xffffffffu, rowacc1, 2);
            if (tg == 0) {
                atomicAdd(&red[wm * 64 + m * 16 + g], rowacc0);
                atomicAdd(&red[wm * 64 + m * 16 + g + 8], rowacc1);
            }
        }
#pragma unroll
        for (int n = 0; n < 4; n++) {
            float c0 = colacc[n][0], c1 = colacc[n][1];
            // reduce col sums across g (lane bits 2-4)
            c0 += __shfl_xor_sync(0xffffffffu, c0, 4);
            c0 += __shfl_xor_sync(0xffffffffu, c0, 8);
            c0 += __shfl_xor_sync(0xffffffffu, c0, 16);
            c1 += __shfl_xor_sync(0xffffffffu, c1, 4);
            c1 += __shfl_xor_sync(0xffffffffu, c1, 8);
            c1 += __shfl_xor_sync(0xffffffffu, c1, 16);
            if (g == 0) {
                atomicAdd(&red[128 + wn * 32 + n * 8 + 2 * tg], c0);
                atomicAdd(&red[128 + wn * 32 + n * 8 + 2 * tg + 1], c1);
            }
        }
        __syncthreads();
        const int S = BHN * SEQ;
        if (tid < 128)
            csump[(long long)blockIdx.x * S + blockIdx.z * SEQ + i0 + tid] = red[tid];
        else
            rsump[(long long)blockIdx.y * S + blockIdx.z * SEQ + j0 + (tid - 128)] = red[tid - 128 + 128];
        return;
    }

    // ---- standard epilogue: direct reg -> gmem (v2 stores) ----
#pragma unroll
    for (int m = 0; m < 4; m++) {
        int r0 = i0 + wm * 64 + m * 16 + g;
#pragma unroll
        for (int n = 0; n < 4; n++) {
            int gj = j0 + wn * 32 + n * 8 + 2 * tg;
            if (gj >= N) continue;
            float2 v0 = make_float2(acc[m][n][0] * alpha, acc[m][n][1] * alpha);
            float2 v1 = make_float2(acc[m][n][2] * alpha, acc[m][n][3] * alpha);
            if (EPI == 2) {
                float2 bv = *(const float2*)(bias + gj);
                v0.x += bv.x; v0.y += bv.y; v1.x += bv.x; v1.y += bv.y;
            }
            if (RND) {
                v0.x = cvt_tf32(v0.x); v0.y = cvt_tf32(v0.y);
                v1.x = cvt_tf32(v1.x); v1.y = cvt_tf32(v1.y);
            }
            if (EPI == 1) {
                int s_  = gj / DIMC;
                int rc  = gj - s_ * DIMC;
                int h   = rc >> 8;
                int d   = rc & 255;
#pragma unroll
                for (int hh = 0; hh < 2; hh++) {
                    int gi = r0 + hh * 8;
                    if (gi >= M) continue;
                    int b_ = gi / SEQ, nn = gi - b_ * SEQ;
                    long long dst = ((((long long)s_ * BHN) + (b_ * NH + h)) * SEQ + nn) * HDIM + d;
                    *(float2*)&C[dst] = hh ? v1 : v0;
                }
            } else {
                if (r0 < M)     *(float2*)&C[(long long)r0 * ldc + gj] = v0;
                if (r0 + 8 < M) *(float2*)&C[(long long)(r0 + 8) * ldc + gj] = v1;
            }
        }
    }
}

// ---------------------------------------------------------------------------
// Prep: tf32-round copies of external inputs
// ---------------------------------------------------------------------------
__global__ void round_copy4(const float4* __restrict__ src, float4* __restrict__ dst, int n4)
{
    int i = blockIdx.x * 256 + threadIdx.x;
    if (i >= n4) return;
    float4 v = src[i];
    v.x = cvt_tf32(v.x); v.y = cvt_tf32(v.y); v.z = cvt_tf32(v.z); v.w = cvt_tf32(v.w);
    dst[i] = v;
}

__global__ void pad_round_wpf(const float* __restrict__ W, float* __restrict__ out)
{
    int idx = blockIdx.x * 256 + threadIdx.x;
    if (idx >= DIMC * HD3P) return;
    int o = idx / HD3P, j = idx - o * HD3P;
    out[idx] = (j < HD3) ? cvt_tf32(W[o * HD3 + j]) : 0.f;
}

// ---------------------------------------------------------------------------
// Combine NPART partial sums -> reciprocal
// ---------------------------------------------------------------------------
__global__ void part_comb(const float* __restrict__ part, float* __restrict__ inv)
{
    const int idx = blockIdx.x * 256 + threadIdx.x;
    if (idx >= BHN * SEQ) return;
    float s = 0.f;
#pragma unroll
    for (int p = 0; p < NPART; p++) s += part[(long long)p * (BHN * SEQ) + idx];
    inv[idx] = 1.f / s;
}

// ---------------------------------------------------------------------------
// attn_f^T[m][n] = e^2 * rinv[n] * cinv[m], tf32-rounded in place (no exp!)
// ---------------------------------------------------------------------------
__global__ void apply_softmax(float4* __restrict__ attn,
                              const float* __restrict__ rinv, const float* __restrict__ cinv)
{
    const long long id = (long long)blockIdx.x * blockDim.x + threadIdx.x;
    if (id >= (long long)BHN * SEQ * SEQ / 4) return;
    const long long base = id * 4;
    const int n0 = (int)(base % SEQ);
    const long long rg = base / SEQ;        // bh*SEQ + m
    const int bh = (int)(rg / SEQ);

    const float ci = cinv[rg];
    const float4 ri = *(const float4*)(rinv + (long long)bh * SEQ + n0);

    float4 v = attn[id];
    v.x = cvt_tf32(v.x * v.x * ri.x * ci);
    v.y = cvt_tf32(v.y * v.y * ri.y * ci);
    v.z = cvt_tf32(v.z * v.z * ri.z * ci);
    v.w = cvt_tf32(v.w * v.w * ri.w * ci);
    attn[id] = v;
}

// ---------------------------------------------------------------------------
// vcatT[bh][d][n] = v[bh][n][d]  (32x32 smem transpose; src already rounded)
// ---------------------------------------------------------------------------
__global__ void build_vcatT(const float* __restrict__ qkvP, float* __restrict__ vcatT)
{
    __shared__ float t[32][33];
    const int bh = blockIdx.z;
    const int n0 = blockIdx.x * 32;
    const int d0 = blockIdx.y * 32;
    const float* src = qkvP + ((long long)(2 * BHN + bh) * SEQ) * HDIM;
    float* dst = vcatT + (long long)bh * DD * SEQ;
#pragma unroll
    for (int k = 0; k < 4; k++) {
        int n = n0 + threadIdx.y + k * 8;
        t[threadIdx.y + k * 8][threadIdx.x] = src[(long long)n * HDIM + d0 + threadIdx.x];
    }
    __syncthreads();
#pragma unroll
    for (int k = 0; k < 4; k++) {
        int d = d0 + threadIdx.y + k * 8;
        dst[(long long)d * SEQ + n0 + threadIdx.x] = t[threadIdx.x][threadIdx.y + k * 8];
    }
}

__global__ void build_pos(float* __restrict__ vcatT)
{
    const int n  = blockIdx.x * 256 + threadIdx.x;
    const int bh = blockIdx.y;
    int iy = n % 48;
    int ix = n / 48;
    float y = -1.f + 2.f * (float)iy / 47.f;
    float x = -1.f + 2.f * (float)ix / 63.f;
    float* dst = vcatT + (long long)bh * DD * SEQ + n;
    dst[(long long)(HDIM + 0) * SEQ] = cvt_tf32(y * y);
    dst[(long long)(HDIM + 1) * SEQ] = cvt_tf32(x * x);
    dst[(long long)(HDIM + 2) * SEQ] = cvt_tf32(y * x);
    dst[(long long)(HDIM + 3) * SEQ] = cvt_tf32(y);
    dst[(long long)(HDIM + 4) * SEQ] = cvt_tf32(x);
    dst[(long long)(HDIM + 5) * SEQ] = 1.f;
}

// ---------------------------------------------------------------------------
// f1 positional rows: f1[bh][256+j][m] = sum_n p[j][n] * attn_f[bh][m][n]
// p rows cached in smem (identical across bh -> read from bh 0 of vcatT).
// Block: 256 threads = 8 warps, each warp 4 m-rows. Grid (SEQ/32, BHN).
// ---------------------------------------------------------------------------
__global__ void __launch_bounds__(256) f1_pos(
    const float* __restrict__ attnf, const float* __restrict__ vcatT,
    float* __restrict__ f1)
{
    __shared__ float ps[6][1024];
    const int bh  = blockIdx.y;
    const int m0  = blockIdx.x * 32;
    const int tid = threadIdx.x, wid = tid >> 5, lane = tid & 31;

    float acc[4][6];
#pragma unroll
    for (int rr = 0; rr < 4; rr++)
#pragma unroll
        for (int j = 0; j < 6; j++) acc[rr][j] = 0.f;

    const float* pbase = vcatT + (long long)HDIM * SEQ;   // bh 0, rows 256..261

    for (int c = 0; c < 3; c++) {
        const int n0c = c * 1024;
        __syncthreads();
#pragma unroll
        for (int j = 0; j < 6; j++)
            *(float4*)&ps[j][tid * 4] = *(const float4*)(pbase + (long long)j * SEQ + n0c + tid * 4);
        __syncthreads();
#pragma unroll
        for (int rr = 0; rr < 4; rr++) {
            const int m = m0 + wid * 4 + rr;
            const float* arow = attnf + ((long long)bh * SEQ + m) * SEQ + n0c;
#pragma unroll
            for (int q = 0; q < 8; q++) {
                const int nl = lane * 4 + q * 128;
                float4 a = *(const float4*)(arow + nl);
#pragma unroll
                for (int j = 0; j < 6; j++) {
                    float4 p4 = *(const float4*)&ps[j][nl];
                    acc[rr][j] += a.x * p4.x + a.y * p4.y + a.z * p4.z + a.w * p4.w;
                }
            }
        }
    }
#pragma unroll
    for (int rr = 0; rr < 4; rr++) {
        const int m = m0 + wid * 4 + rr;
#pragma unroll
        for (int j = 0; j < 6; j++) {
            float s = acc[rr][j];
            for (int o = 16; o; o >>= 1) s += __shfl_xor_sync(0xffffffffu, s, o);
            if (lane == 0)
                f1[((long long)bh * DD + HDIM + j) * SEQ + m] = cvt_tf32(s);
        }
    }
}

// ---------------------------------------------------------------------------
// fundT[b][e][h*DD+d] = fund[bh][d][e]  (rounded, padded ld)
// ---------------------------------------------------------------------------
__global__ void transpose_fund(const float* __restrict__ fund, float* __restrict__ fundT)
{
    const long long idx = (long long)blockIdx.x * blockDim.x + threadIdx.x;
    if (idx >= (long long)BHN * DD * DD) return;
    const int e  = (int)(idx % DD);
    const long long r = idx / DD;
    const int d  = (int)(r % DD);
    const int bh = (int)(r / DD);
    const int b  = bh / NH;
    const int h  = bh - b * NH;
    fundT[((long long)b * DD + e) * HD3P + h * DD + d] = cvt_tf32(fund[idx]);
}

__global__ void zero_pad_fundT(float* __restrict__ fundT)
{
    const int idx = blockIdx.x * 256 + threadIdx.x;
    if (idx >= BB * DD * 2) return;
    int p = idx & 1, row = idx >> 1;
    fundT[(long long)row * HD3P + HD3 + p] = 0.f;
}

// ---------------------------------------------------------------------------
// Launch
// ---------------------------------------------------------------------------
extern "C" void kernel_launch(void* const* d_in, const int* in_sizes, int n_in,
                              void* d_out, int out_size)
{
    const float* x    = (const float*)d_in[0];  // [4,3072,768]
    const float* Wqkv = (const float*)d_in[1];  // [2304,768]
    const float* Wpf  = (const float*)d_in[2];  // [768,786]
    const float* bpf  = (const float*)d_in[3];  // [768]
    float* out = (float*)d_out;                 // [4,262,768]

    float *qkvP, *attn, *vcatT, *f1, *fund, *fundT, *xr, *wqkvr, *wpfr;
    float *rinv, *cinv, *csump, *rsump;
    cudaGetSymbolAddress((void**)&qkvP,  g_qkvP);
    cudaGetSymbolAddress((void**)&attn,  g_attn);
    cudaGetSymbolAddress((void**)&vcatT, g_vcatT);
    cudaGetSymbolAddress((void**)&f1,    g_f1);
    cudaGetSymbolAddress((void**)&fund,  g_fund);
    cudaGetSymbolAddress((void**)&fundT, g_fundT);
    cudaGetSymbolAddress((void**)&xr,    g_xr);
    cudaGetSymbolAddress((void**)&wqkvr, g_wqkvr);
    cudaGetSymbolAddress((void**)&wpfr,  g_wpfr);
    cudaGetSymbolAddress((void**)&rinv,  g_rinv);
    cudaGetSymbolAddress((void**)&cinv,  g_cinv);
    cudaGetSymbolAddress((void**)&csump, g_csump);
    cudaGetSymbolAddress((void**)&rsump, g_rsump);

    cudaFuncSetAttribute(ca_gemm<0,0>, cudaFuncAttributeMaxDynamicSharedMemorySize, SMEM_TOTAL);
    cudaFuncSetAttribute(ca_gemm<0,1>, cudaFuncAttributeMaxDynamicSharedMemorySize, SMEM_TOTAL);
    cudaFuncSetAttribute(ca_gemm<1,1>, cudaFuncAttributeMaxDynamicSharedMemorySize, SMEM_TOTAL);
    cudaFuncSetAttribute(ca_gemm<2,0>, cudaFuncAttributeMaxDynamicSharedMemorySize, SMEM_TOTAL);
    cudaFuncSetAttribute(ca_gemm<3,0>, cudaFuncAttributeMaxDynamicSharedMemorySize, SMEM_TOTAL);

    const long long sQ = (long long)SEQ * HDIM;

    // 0) tf32-round external operands
    round_copy4<<<(BB * SEQ * DIMC / 4 + 255) / 256, 256>>>(
        (const float4*)x, (float4*)xr, BB * SEQ * DIMC / 4);
    round_copy4<<<(3 * DIMC * DIMC / 4 + 255) / 256, 256>>>(
        (const float4*)Wqkv, (float4*)wqkvr, 3 * DIMC * DIMC / 4);
    pad_round_wpf<<<(DIMC * HD3P + 255) / 256, 256>>>(Wpf, wpfr);

    // 1) QKV projection, scattered (rounded) to [s][bh][n][d]
    ca_gemm<1,1><<<dim3((3 * DIMC) / 128, (BB * SEQ) / 128, 1), 256, SMEM_TOTAL>>>(
        xr, wqkvr, qkvP, nullptr,
        BB * SEQ, 3 * DIMC, DIMC, DIMC, DIMC, 0, 0, 0, 0, 1.f, nullptr, nullptr);

    // 2) attnT[m][n] = exp(scale * k_m . q_n) + fused row/col partial sums
    ca_gemm<3,0><<<dim3(SEQ / 128, SEQ / 128, BHN), 256, SMEM_TOTAL>>>(
        qkvP + (long long)BHN * sQ, qkvP, attn, nullptr,
        SEQ, SEQ, HDIM, HDIM, HDIM, SEQ,
        sQ, sQ, (long long)SEQ * SEQ, 0.0625f, csump, rsump);

    // 3) combine partials -> reciprocals
    part_comb<<<(BHN * SEQ + 255) / 256, 256>>>(csump, cinv);
    part_comb<<<(BHN * SEQ + 255) / 256, 256>>>(rsump, rinv);

    // 4) attn_f^T = e^2 * rinv * cinv, in place (tf32-rounded)
    apply_softmax<<<(unsigned)(((long long)BHN * SEQ * SEQ / 4 + 255) / 256), 256>>>(
        (float4*)attn, rinv, cinv);

    // 5) vcatT = [v; pos]^T
    build_vcatT<<<dim3(SEQ / 32, HDIM / 32, BHN), dim3(32, 8)>>>(qkvP, vcatT);
    build_pos<<<dim3(SEQ / 256, BHN), 256>>>(vcatT);

    // 6) f1 v-rows (M=256, zero padding waste) + positional rows (thin kernel)
    ca_gemm<0,1><<<dim3(SEQ / 128, HDIM / 128, BHN), 256, SMEM_TOTAL>>>(
        vcatT, attn, f1, nullptr,
        HDIM, SEQ, SEQ, SEQ, SEQ, SEQ,
        (long long)DD * SEQ, (long long)SEQ * SEQ, (long long)DD * SEQ, 1.f, nullptr, nullptr);
    f1_pos<<<dim3(SEQ / 32, BHN), 256>>>(attn, vcatT, f1);

    // 7) fund[d][e] = sum_m f1[d][m] * vcatT[e][m]
    ca_gemm<0,0><<<dim3((DD + 127) / 128, (DD + 127) / 128, BHN), 256, SMEM_TOTAL>>>(
        f1, vcatT, fund, nullptr,
        DD, DD, SEQ, SEQ, SEQ, DD,
        (long long)DD * SEQ, (long long)DD * SEQ, (long long)DD * DD, 1.f, nullptr, nullptr);

    // 8) reshape/transpose (rounded, padded)
    transpose_fund<<<(int)(((long long)BHN * DD * DD + 255) / 256), 256>>>(fund, fundT);
    zero_pad_fundT<<<(BB * DD * 2 + 255) / 256, 256>>>(fundT);

    // 9) out[b][e][o] = sum_j fundT[b][e][j] * Wpf[o][j] + bpf[o]
    ca_gemm<2,0><<<dim3(DIMC / 128, (DD + 127) / 128, BB), 256, SMEM_TOTAL>>>(
        fundT, wpfr, out, bpf,
        DD, DIMC, HD3, HD3P, HD3P, DIMC,
        (long long)DD * HD3P, 0, (long long)DD * DIMC, 1.f, nullptr, nullptr);
}

// round 11
// speedup vs baseline: 5.6417x; 1.0706x over previous
#include <cuda_runtime.h>
#include <math.h>
#include <cstdint>

// ---------------------------------------------------------------------------
// Problem constants
// ---------------------------------------------------------------------------
#define BB    4
#define SEQ   3072
#define DIMC  768
#define NH    3
#define HDIM  256
#define DD    262
#define BHN   12
#define HD3   786
#define HD3P  788          // padded to 16B-aligned rows
#define NPART (SEQ / 128)  // 24 partial sums per row/col

// ---------------------------------------------------------------------------
// Scratch (device globals: sanctioned alloc-free scratch)
// ---------------------------------------------------------------------------
static __device__ float g_qkvP[(size_t)3 * BHN * SEQ * HDIM];  // [s][bh][n][d] (tf32-rounded)
static __device__ float g_attn[(size_t)BHN * SEQ * SEQ];       // attnT: [bh][m][n] = e^2 (tf32)
static __device__ float g_vcatR[(size_t)BHN * DD * SEQ];       // [bh][e][n] * rinv[n] (rounded)
static __device__ float g_vcatC[(size_t)BHN * DD * SEQ];       // [bh][e][m] * cinv[m] (rounded)
static __device__ float g_f1  [(size_t)BHN * DD * SEQ];        // [bh][d][m] (rounded, no cinv)
static __device__ float g_fundT[(size_t)BB * DD * HD3P];       // padded ld (rounded)
static __device__ float g_xr[(size_t)BB * SEQ * DIMC];         // rounded x
static __device__ float g_wqkvr[(size_t)3 * DIMC * DIMC];      // rounded W_qkv
static __device__ float g_wpfr[(size_t)DIMC * HD3P];           // rounded+padded W_pf
static __device__ float g_rinv[BHN * SEQ];                     // 1/col-sum (per n)
static __device__ float g_cinv[BHN * SEQ];                     // 1/row-sum (per m)
static __device__ float g_csump[(size_t)NPART * BHN * SEQ];    // partial row-sums (per m)
static __device__ float g_rsump[(size_t)NPART * BHN * SEQ];    // partial col-sums (per n)

// ---------------------------------------------------------------------------
// Helpers (plain sm_80-era PTX; nothing "a"-gated)
// ---------------------------------------------------------------------------
__device__ __forceinline__ uint32_t smem_u32(const void* p) {
    uint32_t a;
    asm("{ .reg .u64 t; cvta.to.shared.u64 t, %1; cvt.u32.u64 %0, t; }" : "=r"(a) : "l"(p));
    return a;
}
__device__ __forceinline__ float cvt_tf32(float x) {
    float y; asm("cvt.rna.tf32.f32 %0, %1;" : "=f"(y) : "f"(x)); return y;
}
__device__ __forceinline__ void cp16(uint32_t dst, const void* src, int srcbytes) {
    asm volatile("cp.async.cg.shared.global [%0], [%1], 16, %2;"
                 :: "r"(dst), "l"(src), "r"(srcbytes));
}
__device__ __forceinline__ void cp_commit() { asm volatile("cp.async.commit_group;"); }
__device__ __forceinline__ void cp_wait1()  { asm volatile("cp.async.wait_group 1;"); }
__device__ __forceinline__ void cp_wait0()  { asm volatile("cp.async.wait_group 0;"); }

#define LDSM_X4(r, addr) \
    asm volatile("ldmatrix.sync.aligned.m8n8.x4.shared.b16 {%0,%1,%2,%3}, [%4];" \
        : "=r"((r)[0]), "=r"((r)[1]), "=r"((r)[2]), "=r"((r)[3]) : "r"(addr))

#define MMA_TF32(c, a, b0v, b1v) \
    asm volatile("mma.sync.aligned.m16n8k8.row.col.f32.tf32.tf32.f32 " \
        "{%0,%1,%2,%3}, {%4,%5,%6,%7}, {%8,%9}, {%0,%1,%2,%3};" \
        : "+f"((c)[0]), "+f"((c)[1]), "+f"((c)[2]), "+f"((c)[3]) \
        : "r"((a)[0]), "r"((a)[1]), "r"((a)[2]), "r"((a)[3]), "r"(b0v), "r"(b1v))

// ---------------------------------------------------------------------------
// tf32 tensor-core GEMM, cp.async 3-stage pipeline.
// C[i,j] = alpha * sum_k A(i,k)*B(j,k); operands PRE-ROUNDED to tf32 in gmem.
// CTA tile 128x128, K-tile 32, 256 threads (8 warps, 64Mx32N warptile).
// EPI 0: plain store; EPI 1: QKV scatter; EPI 2: +bias[j];
// EPI 3: store tf32(e^2), e=exp(v*alpha), + per-CTA row/col partial sums of e;
// EPI 4: transposed scatter into fundT[b][e][h*DD+d].
// RND: tf32-round output.
// ---------------------------------------------------------------------------
#define STAGE_STRIDE 32768u
static constexpr unsigned SMEM_TOTAL = 3 * STAGE_STRIDE;   // 96 KB

__device__ __forceinline__ void issue_stage(
    const float* __restrict__ A, const float* __restrict__ B, uint32_t sb, int kt,
    int i0, int j0, int M, int N, int K, int lda, int ldb, int u, int rs)
{
    const uint32_t aB = sb + (uint32_t)(kt % 3) * STAGE_STRIDE;
    const uint32_t bB = aB + 16384u;
    const int kk  = kt * 32 + u * 4;
    const int rem = K - kk;
    const int bytes = rem >= 4 ? 16 : (rem > 0 ? rem * 4 : 0);
    const uint32_t csw = (uint32_t)(u * 16);
#pragma unroll
    for (int it = 0; it < 4; it++) {
        int r = rs + it * 32;
        uint32_t off = (uint32_t)(r * 128) + (csw ^ (uint32_t)((r & 7) << 4));
        int gia = i0 + r, gib = j0 + r;
        const float* pa = A + (long long)(gia < M ? gia : 0) * lda + kk;
        const float* pb = B + (long long)(gib < N ? gib : 0) * ldb + kk;
        cp16(aB + off, pa, gia < M ? bytes : 0);
        cp16(bB + off, pb, gib < N ? bytes : 0);
    }
    cp_commit();
}

template<int EPI, int RND>
__global__ void __launch_bounds__(256, 2) ca_gemm(
    const float* __restrict__ A, const float* __restrict__ B,
    float* __restrict__ C, const float* __restrict__ bias,
    int M, int N, int K, int lda, int ldb, int ldc,
    long long sA, long long sB, long long sC, float alpha,
    float* __restrict__ csump, float* __restrict__ rsump)
{
    extern __shared__ char smem[];
    const uint32_t sb = smem_u32(smem);

    A += (long long)blockIdx.z * sA;
    B += (long long)blockIdx.z * sB;
    if (EPI != 1) C += (long long)blockIdx.z * sC;
    const int i0 = blockIdx.y * 128;
    const int j0 = blockIdx.x * 128;

    const int tid  = threadIdx.x;
    const int wid  = tid >> 5, lane = tid & 31;
    const int wm   = wid >> 2, wn = wid & 3;
    const int g    = lane >> 2, tg = lane & 3;
    const int sub  = lane >> 3, l  = lane & 7;
    const int u    = tid & 7,  rs  = tid >> 3;

    const int halfA = sub >> 1;
    const int halfB = sub & 1;
    uint32_t laOff[4], la7[4], lbOff[2], lb7[2];
#pragma unroll
    for (int m = 0; m < 4; m++) {
        int r = wm * 64 + m * 16 + (sub & 1) * 8 + l;
        laOff[m] = (uint32_t)(r * 128); la7[m] = (uint32_t)(r & 7);
    }
#pragma unroll
    for (int p = 0; p < 2; p++) {
        int r = wn * 32 + p * 16 + (sub >> 1) * 8 + l;
        lbOff[p] = (uint32_t)(r * 128); lb7[p] = (uint32_t)(r & 7);
    }

    float acc[4][4][4];
#pragma unroll
    for (int m = 0; m < 4; m++)
#pragma unroll
        for (int n = 0; n < 4; n++)
#pragma unroll
            for (int e = 0; e < 4; e++) acc[m][n][e] = 0.f;

    const int nk = (K + 31) / 32;
    issue_stage(A, B, sb, 0, i0, j0, M, N, K, lda, ldb, u, rs);
    if (nk > 1) issue_stage(A, B, sb, 1, i0, j0, M, N, K, lda, ldb, u, rs);

    for (int kt = 0; kt < nk; kt++) {
        if (kt + 1 < nk) cp_wait1(); else cp_wait0();
        __syncthreads();
        if (kt + 2 < nk)
            issue_stage(A, B, sb, kt + 2, i0, j0, M, N, K, lda, ldb, u, rs);

        const uint32_t aB = sb + (uint32_t)(kt % 3) * STAGE_STRIDE;
        const uint32_t bB = aB + 16384u;
#pragma unroll
        for (int ks = 0; ks < 4; ks++) {
            uint32_t af[4][4], bf[2][4];
#pragma unroll
            for (int m = 0; m < 4; m++) {
                uint32_t ch = (uint32_t)(ks * 2 + halfA) ^ la7[m];
                LDSM_X4(af[m], aB + laOff[m] + (ch << 4));
            }
#pragma unroll
            for (int p = 0; p < 2; p++) {
                uint32_t ch = (uint32_t)(ks * 2 + halfB) ^ lb7[p];
                LDSM_X4(bf[p], bB + lbOff[p] + (ch << 4));
            }
#pragma unroll
            for (int m = 0; m < 4; m++) {
#pragma unroll
                for (int n = 0; n < 4; n++)
                    MMA_TF32(acc[m][n], af[m], bf[n >> 1][(n & 1) * 2], bf[n >> 1][(n & 1) * 2 + 1]);
            }
        }
    }

    if (EPI == 3) {
        // ---- softmax-fused epilogue: store tf32(e^2), reduce partial sums of e ----
        __syncthreads();
        float* red = (float*)smem;            // [0:128) row sums, [128:256) col sums
        red[tid] = 0.f;
        __syncthreads();

        float colacc[4][2];
#pragma unroll
        for (int n = 0; n < 4; n++) { colacc[n][0] = 0.f; colacc[n][1] = 0.f; }

#pragma unroll
        for (int m = 0; m < 4; m++) {
            int r0 = i0 + wm * 64 + m * 16 + g;
            float rowacc0 = 0.f, rowacc1 = 0.f;
#pragma unroll
            for (int n = 0; n < 4; n++) {
                int gj = j0 + wn * 32 + n * 8 + 2 * tg;
                float e0 = __expf(acc[m][n][0] * alpha);
                float e1 = __expf(acc[m][n][1] * alpha);
                float e2 = __expf(acc[m][n][2] * alpha);
                float e3 = __expf(acc[m][n][3] * alpha);
                *(float2*)&C[(long long)r0 * ldc + gj] =
                    make_float2(cvt_tf32(e0 * e0), cvt_tf32(e1 * e1));
                *(float2*)&C[(long long)(r0 + 8) * ldc + gj] =
                    make_float2(cvt_tf32(e2 * e2), cvt_tf32(e3 * e3));
                rowacc0 += e0 + e1; rowacc1 += e2 + e3;
                colacc[n][0] += e0 + e2; colacc[n][1] += e1 + e3;
            }
            rowacc0 += __shfl_xor_sync(0xffffffffu, rowacc0, 1);
            rowacc0 += __shfl_xor_sync(0xffffffffu, rowacc0, 2);
            rowacc1 += __shfl_xor_sync(0xffffffffu, rowacc1, 1);
            rowacc1 += __shfl_xor_sync(0xffffffffu, rowacc1, 2);
            if (tg == 0) {
                atomicAdd(&red[wm * 64 + m * 16 + g], rowacc0);
                atomicAdd(&red[wm * 64 + m * 16 + g + 8], rowacc1);
            }
        }
#pragma unroll
        for (int n = 0; n < 4; n++) {
            float c0 = colacc[n][0], c1 = colacc[n][1];
            c0 += __shfl_xor_sync(0xffffffffu, c0, 4);
            c0 += __shfl_xor_sync(0xffffffffu, c0, 8);
            c0 += __shfl_xor_sync(0xffffffffu, c0, 16);
            c1 += __shfl_xor_sync(0xffffffffu, c1, 4);
            c1 += __shfl_xor_sync(0xffffffffu, c1, 8);
            c1 += __shfl_xor_sync(0xffffffffu, c1, 16);
            if (g == 0) {
                atomicAdd(&red[128 + wn * 32 + n * 8 + 2 * tg], c0);
                atomicAdd(&red[128 + wn * 32 + n * 8 + 2 * tg + 1], c1);
            }
        }
        __syncthreads();
        const int S = BHN * SEQ;
        if (tid < 128)
            csump[(long long)blockIdx.x * S + blockIdx.z * SEQ + i0 + tid] = red[tid];
        else
            rsump[(long long)blockIdx.y * S + blockIdx.z * SEQ + j0 + (tid - 128)] = red[tid];
        return;
    }

    // ---- standard / scatter epilogues ----
    int bF = 0, hF = 0;
    if (EPI == 4) { bF = blockIdx.z / NH; hF = blockIdx.z - bF * NH; }
#pragma unroll
    for (int m = 0; m < 4; m++) {
        int r0 = i0 + wm * 64 + m * 16 + g;
#pragma unroll
        for (int n = 0; n < 4; n++) {
            int gj = j0 + wn * 32 + n * 8 + 2 * tg;
            if (gj >= N) continue;
            float2 v0 = make_float2(acc[m][n][0] * alpha, acc[m][n][1] * alpha);
            float2 v1 = make_float2(acc[m][n][2] * alpha, acc[m][n][3] * alpha);
            if (EPI == 2) {
                float2 bv = *(const float2*)(bias + gj);
                v0.x += bv.x; v0.y += bv.y; v1.x += bv.x; v1.y += bv.y;
            }
            if (RND) {
                v0.x = cvt_tf32(v0.x); v0.y = cvt_tf32(v0.y);
                v1.x = cvt_tf32(v1.x); v1.y = cvt_tf32(v1.y);
            }
            if (EPI == 1) {
                int s_  = gj / DIMC;
                int rc  = gj - s_ * DIMC;
                int h   = rc >> 8;
                int d   = rc & 255;
#pragma unroll
                for (int hh = 0; hh < 2; hh++) {
                    int gi = r0 + hh * 8;
                    if (gi >= M) continue;
                    int b_ = gi / SEQ, nn = gi - b_ * SEQ;
                    long long dst = ((((long long)s_ * BHN) + (b_ * NH + h)) * SEQ + nn) * HDIM + d;
                    *(float2*)&C[dst] = hh ? v1 : v0;
                }
            } else if (EPI == 4) {
                // fundT[bF][gj(=e)][hF*DD + gi(=d)]
                if (r0 < M) {
                    C[((long long)(bF * DD + gj)) * HD3P + hF * DD + r0] = v0.x;
                    if (gj + 1 < N)
                        C[((long long)(bF * DD + gj + 1)) * HD3P + hF * DD + r0] = v0.y;
                }
                if (r0 + 8 < M) {
                    C[((long long)(bF * DD + gj)) * HD3P + hF * DD + r0 + 8] = v1.x;
                    if (gj + 1 < N)
                        C[((long long)(bF * DD + gj + 1)) * HD3P + hF * DD + r0 + 8] = v1.y;
                }
            } else {
                if (r0 < M)     *(float2*)&C[(long long)r0 * ldc + gj] = v0;
                if (r0 + 8 < M) *(float2*)&C[(long long)(r0 + 8) * ldc + gj] = v1;
            }
        }
    }
}

// ---------------------------------------------------------------------------
// Prep: tf32-round copies of external inputs
// ---------------------------------------------------------------------------
__global__ void round_copy4(const float4* __restrict__ src, float4* __restrict__ dst, int n4)
{
    int i = blockIdx.x * 256 + threadIdx.x;
    if (i >= n4) return;
    float4 v = src[i];
    v.x = cvt_tf32(v.x); v.y = cvt_tf32(v.y); v.z = cvt_tf32(v.z); v.w = cvt_tf32(v.w);
    dst[i] = v;
}

__global__ void pad_round_wpf(const float* __restrict__ W, float* __restrict__ out)
{
    int idx = blockIdx.x * 256 + threadIdx.x;
    if (idx >= DIMC * HD3P) return;
    int o = idx / HD3P, j = idx - o * HD3P;
    out[idx] = (j < HD3) ? cvt_tf32(W[o * HD3 + j]) : 0.f;
}

// ---------------------------------------------------------------------------
// Combine NPART partial sums -> reciprocal
// ---------------------------------------------------------------------------
__global__ void part_comb(const float* __restrict__ part, float* __restrict__ inv)
{
    const int idx = blockIdx.x * 256 + threadIdx.x;
    if (idx >= BHN * SEQ) return;
    float s = 0.f;
#pragma unroll
    for (int p = 0; p < NPART; p++) s += part[(long long)p * (BHN * SEQ) + idx];
    inv[idx] = 1.f / s;
}

// ---------------------------------------------------------------------------
// vcatR[bh][d][n] = v[bh][n][d]*rinv[n];  vcatC[bh][d][n] = v[bh][n][d]*cinv[n]
// (32x32 smem transpose; both outputs tf32-rounded)
// ---------------------------------------------------------------------------
__global__ void build_vcat2(const float* __restrict__ qkvP,
                            const float* __restrict__ rinv, const float* __restrict__ cinv,
                            float* __restrict__ vcatR, float* __restrict__ vcatC)
{
    __shared__ float t[32][33];
    const int bh = blockIdx.z;
    const int n0 = blockIdx.x * 32;
    const int d0 = blockIdx.y * 32;
    const float* src = qkvP + ((long long)(2 * BHN + bh) * SEQ) * HDIM;
#pragma unroll
    for (int k = 0; k < 4; k++) {
        int n = n0 + threadIdx.y + k * 8;
        t[threadIdx.y + k * 8][threadIdx.x] = src[(long long)n * HDIM + d0 + threadIdx.x];
    }
    __syncthreads();
    const int n = n0 + threadIdx.x;
    const float rs = rinv[bh * SEQ + n];
    const float cs = cinv[bh * SEQ + n];
    float* dR = vcatR + (long long)bh * DD * SEQ;
    float* dC = vcatC + (long long)bh * DD * SEQ;
#pragma unroll
    for (int k = 0; k < 4; k++) {
        int d = d0 + threadIdx.y + k * 8;
        float v = t[threadIdx.x][threadIdx.y + k * 8];
        dR[(long long)d * SEQ + n] = cvt_tf32(v * rs);
        dC[(long long)d * SEQ + n] = cvt_tf32(v * cs);
    }
}

// positional rows e = 256..261 of vcatR/vcatC (scaled per-bh)
__global__ void build_pos2(const float* __restrict__ rinv, const float* __restrict__ cinv,
                           float* __restrict__ vcatR, float* __restrict__ vcatC)
{
    const int n  = blockIdx.x * 256 + threadIdx.x;
    const int bh = blockIdx.y;
    int iy = n % 48;
    int ix = n / 48;
    float y = -1.f + 2.f * (float)iy / 47.f;
    float x = -1.f + 2.f * (float)ix / 63.f;
    float p[6] = { y * y, x * x, y * x, y, x, 1.f };
    const float rs = rinv[bh * SEQ + n];
    const float cs = cinv[bh * SEQ + n];
    float* dR = vcatR + (long long)bh * DD * SEQ + n;
    float* dC = vcatC + (long long)bh * DD * SEQ + n;
#pragma unroll
    for (int j = 0; j < 6; j++) {
        dR[(long long)(HDIM + j) * SEQ] = cvt_tf32(p[j] * rs);
        dC[(long long)(HDIM + j) * SEQ] = cvt_tf32(p[j] * cs);
    }
}

// ---------------------------------------------------------------------------
// f1 positional rows: f1[bh][256+j][m] = sum_n vcatR_pos[bh][j][n] * e2[bh][m][n]
// p rows cached in smem (per-bh now: rinv-scaled). Grid (SEQ/32, BHN).
// ---------------------------------------------------------------------------
__global__ void __launch_bounds__(256) f1_pos(
    const float* __restrict__ attnf, const float* __restrict__ vcatR,
    float* __restrict__ f1)
{
    __shared__ float ps[6][1024];
    const int bh  = blockIdx.y;
    const int m0  = blockIdx.x * 32;
    const int tid = threadIdx.x, wid = tid >> 5, lane = tid & 31;

    float acc[4][6];
#pragma unroll
    for (int rr = 0; rr < 4; rr++)
#pragma unroll
        for (int j = 0; j < 6; j++) acc[rr][j] = 0.f;

    const float* pbase = vcatR + ((long long)bh * DD + HDIM) * SEQ;

    for (int c = 0; c < 3; c++) {
        const int n0c = c * 1024;
        __syncthreads();
#pragma unroll
        for (int j = 0; j < 6; j++)
            *(float4*)&ps[j][tid * 4] = *(const float4*)(pbase + (long long)j * SEQ + n0c + tid * 4);
        __syncthreads();
#pragma unroll
        for (int rr = 0; rr < 4; rr++) {
            const int m = m0 + wid * 4 + rr;
            const float* arow = attnf + ((long long)bh * SEQ + m) * SEQ + n0c;
#pragma unroll
            for (int q = 0; q < 8; q++) {
                const int nl = lane * 4 + q * 128;
                float4 a = *(const float4*)(arow + nl);
#pragma unroll
                for (int j = 0; j < 6; j++) {
                    float4 p4 = *(const float4*)&ps[j][nl];
                    acc[rr][j] += a.x * p4.x + a.y * p4.y + a.z * p4.z + a.w * p4.w;
                }
            }
        }
    }
#pragma unroll
    for (int rr = 0; rr < 4; rr++) {
        const int m = m0 + wid * 4 + rr;
#pragma unroll
        for (int j = 0; j < 6; j++) {
            float s = acc[rr][j];
            for (int o = 16; o; o >>= 1) s += __shfl_xor_sync(0xffffffffu, s, o);
            if (lane == 0)
                f1[((long long)bh * DD + HDIM + j) * SEQ + m] = cvt_tf32(s);
        }
    }
}

__global__ void zero_pad_fundT(float* __restrict__ fundT)
{
    const int idx = blockIdx.x * 256 + threadIdx.x;
    if (idx >= BB * DD * 2) return;
    int p = idx & 1, row = idx >> 1;
    fundT[(long long)row * HD3P + HD3 + p] = 0.f;
}

// ---------------------------------------------------------------------------
// Launch
// ---------------------------------------------------------------------------
extern "C" void kernel_launch(void* const* d_in, const int* in_sizes, int n_in,
                              void* d_out, int out_size)
{
    const float* x    = (const float*)d_in[0];  // [4,3072,768]
    const float* Wqkv = (const float*)d_in[1];  // [2304,768]
    const float* Wpf  = (const float*)d_in[2];  // [768,786]
    const float* bpf  = (const float*)d_in[3];  // [768]
    float* out = (float*)d_out;                 // [4,262,768]

    float *qkvP, *attn, *vcatR, *vcatC, *f1, *fundT, *xr, *wqkvr, *wpfr;
    float *rinv, *cinv, *csump, *rsump;
    cudaGetSymbolAddress((void**)&qkvP,  g_qkvP);
    cudaGetSymbolAddress((void**)&attn,  g_attn);
    cudaGetSymbolAddress((void**)&vcatR, g_vcatR);
    cudaGetSymbolAddress((void**)&vcatC, g_vcatC);
    cudaGetSymbolAddress((void**)&f1,    g_f1);
    cudaGetSymbolAddress((void**)&fundT, g_fundT);
    cudaGetSymbolAddress((void**)&xr,    g_xr);
    cudaGetSymbolAddress((void**)&wqkvr, g_wqkvr);
    cudaGetSymbolAddress((void**)&wpfr,  g_wpfr);
    cudaGetSymbolAddress((void**)&rinv,  g_rinv);
    cudaGetSymbolAddress((void**)&cinv,  g_cinv);
    cudaGetSymbolAddress((void**)&csump, g_csump);
    cudaGetSymbolAddress((void**)&rsump, g_rsump);

    cudaFuncSetAttribute(ca_gemm<0,1>, cudaFuncAttributeMaxDynamicSharedMemorySize, SMEM_TOTAL);
    cudaFuncSetAttribute(ca_gemm<1,1>, cudaFuncAttributeMaxDynamicSharedMemorySize, SMEM_TOTAL);
    cudaFuncSetAttribute(ca_gemm<2,0>, cudaFuncAttributeMaxDynamicSharedMemorySize, SMEM_TOTAL);
    cudaFuncSetAttribute(ca_gemm<3,0>, cudaFuncAttributeMaxDynamicSharedMemorySize, SMEM_TOTAL);
    cudaFuncSetAttribute(ca_gemm<4,1>, cudaFuncAttributeMaxDynamicSharedMemorySize, SMEM_TOTAL);

    const long long sQ = (long long)SEQ * HDIM;

    // 0) tf32-round external operands
    round_copy4<<<(BB * SEQ * DIMC / 4 + 255) / 256, 256>>>(
        (const float4*)x, (float4*)xr, BB * SEQ * DIMC / 4);
    round_copy4<<<(3 * DIMC * DIMC / 4 + 255) / 256, 256>>>(
        (const float4*)Wqkv, (float4*)wqkvr, 3 * DIMC * DIMC / 4);
    pad_round_wpf<<<(DIMC * HD3P + 255) / 256, 256>>>(Wpf, wpfr);

    // 1) QKV projection, scattered (rounded) to [s][bh][n][d]
    ca_gemm<1,1><<<dim3((3 * DIMC) / 128, (BB * SEQ) / 128, 1), 256, SMEM_TOTAL>>>(
        xr, wqkvr, qkvP, nullptr,
        BB * SEQ, 3 * DIMC, DIMC, DIMC, DIMC, 0, 0, 0, 0, 1.f, nullptr, nullptr);

    // 2) attnT[m][n] = tf32(e^2), e = exp(scale * k_m . q_n); fused partial sums of e
    ca_gemm<3,0><<<dim3(SEQ / 128, SEQ / 128, BHN), 256, SMEM_TOTAL>>>(
        qkvP + (long long)BHN * sQ, qkvP, attn, nullptr,
        SEQ, SEQ, HDIM, HDIM, HDIM, SEQ,
        sQ, sQ, (long long)SEQ * SEQ, 0.0625f, csump, rsump);

    // 3) combine partials -> reciprocals
    part_comb<<<(BHN * SEQ + 255) / 256, 256>>>(csump, cinv);
    part_comb<<<(BHN * SEQ + 255) / 256, 256>>>(rsump, rinv);

    // 4) vcatR/vcatC = scaled transposed v_cat (+ pos rows)
    build_vcat2<<<dim3(SEQ / 32, HDIM / 32, BHN), dim3(32, 8)>>>(qkvP, rinv, cinv, vcatR, vcatC);
    build_pos2<<<dim3(SEQ / 256, BHN), 256>>>(rinv, cinv, vcatR, vcatC);

    // 5) f1 v-rows: f1[d][m] = sum_n vcatR[d][n] * e2[m][n]   (+ pos rows kernel)
    ca_gemm<0,1><<<dim3(SEQ / 128, HDIM / 128, BHN), 256, SMEM_TOTAL>>>(
        vcatR, attn, f1, nullptr,
        HDIM, SEQ, SEQ, SEQ, SEQ, SEQ,
        (long long)DD * SEQ, (long long)SEQ * SEQ, (long long)DD * SEQ, 1.f, nullptr, nullptr);
    f1_pos<<<dim3(SEQ / 32, BHN), 256>>>(attn, vcatR, f1);

    // 6) fund[d][e] = sum_m f1[d][m] * vcatC[e][m], scattered into fundT (EPI4)
    ca_gemm<4,1><<<dim3((DD + 127) / 128, (DD + 127) / 128, BHN), 256, SMEM_TOTAL>>>(
        f1, vcatC, fundT, nullptr,
        DD, DD, SEQ, SEQ, SEQ, 0,
        (long long)DD * SEQ, (long long)DD * SEQ, 0, 1.f, nullptr, nullptr);
    zero_pad_fundT<<<(BB * DD * 2 + 255) / 256, 256>>>(fundT);

    // 7) out[b][e][o] = sum_j fundT[b][e][j] * Wpf[o][j] + bpf[o]
    ca_gemm<2,0><<<dim3(DIMC / 128, (DD + 127) / 128, BB), 256, SMEM_TOTAL>>>(
        fundT, wpfr, out, bpf,
        DD, DIMC, HD3, HD3P, HD3P, DIMC,
        (long long)DD * HD3P, 0, (long long)DD * DIMC, 1.f, nullptr, nullptr);
}